// round 5
// baseline (speedup 1.0000x reference)
#include <cuda_runtime.h>
#include <cuda_bf16.h>
#include <cstdint>
#include <cstdio>

#define B_      1024
#define K_      11
#define L_KIN_  128
#define L_SUB_  64
#define L_STR_  128
#define D_SEQ_  1280
#define D_STR_  512
#define EMB_    1792        // D_SEQ + D_STR
#define EMB2_   2564        // 2*D_SEQ + 4
#define M_      (B_ * K_)   // 11264
#define NCHUNK_ 44

// ---------------- GEMM tile config ----------------
#define GBM 128
#define GBN 256
#define GBK 32
#define GSTAGES 3
#define GAS 36                      // A smem row stride (floats)
#define GBS 260                     // B smem row stride (floats)
#define GA_BUF (GBM * GAS)          // 4608
#define GB_BUF (GBK * GBS)          // 8320
#define GSMEM_FLOATS (GSTAGES * (GA_BUF + GB_BUF))   // 38784 -> 155136 B

// ---------------- scratch (device globals) ----------------
__device__ float g_X [(size_t)M_ * EMB2_];
__device__ float g_Y [(size_t)M_ * EMB2_];
__device__ float g_XA[(size_t)M_ * EMB2_];
__device__ float g_XB[(size_t)M_ * EMB2_];
__device__ float g_P1[(size_t)M_ * D_SEQ_];
__device__ float g_P2[(size_t)M_ * D_SEQ_];
__device__ float g_Wr[20936720];     // all 6 weight matrices, tf32-rounded
__device__ float g_kin[(size_t)B_ * D_SEQ_];
__device__ float g_psum[NCHUNK_ * EMB2_];
__device__ float g_psq [NCHUNK_ * EMB2_];
__device__ float g_ss  [8 * EMB2_];

__constant__ float c_props[21 * 4] = {
    0,0,0,0,  1,0,0,0,  0,0,0,0,  0,0,0,0,  1,0,0,0,  0,0,0,0,  0,0,0,0,
    1,0,0,0,  1,0,0,0,  0,0,0,0,  0,0,1,0,  0,0,0,0,  0,0,0,1,  0,0,1,0,
    1,0,0,0,  0,0,0,1,  0,1,0,0,  0,0,0,1,  0,1,0,0,  0,1,0,0,  0,0,0,0
};

__device__ __forceinline__ float tf32r(float x) {
    unsigned u;
    asm("cvt.rna.tf32.f32 %0, %1;" : "=r"(u) : "f"(x));
    return __uint_as_float(u);
}
__device__ __forceinline__ float sigmoidf_(float x) { return 1.f / (1.f + expf(-x)); }

__device__ __forceinline__ void mma_tf32(float* d, const unsigned* a, const unsigned* b) {
    asm volatile(
        "mma.sync.aligned.m16n8k8.row.col.f32.tf32.tf32.f32 "
        "{%0,%1,%2,%3}, {%4,%5,%6,%7}, {%8,%9}, {%0,%1,%2,%3};\n"
        : "+f"(d[0]), "+f"(d[1]), "+f"(d[2]), "+f"(d[3])
        : "r"(a[0]), "r"(a[1]), "r"(a[2]), "r"(a[3]), "r"(b[0]), "r"(b[1]));
}

__device__ __forceinline__ void cp16(unsigned dst, const void* src, bool pred) {
    int sz = pred ? 16 : 0;
    asm volatile("cp.async.cg.shared.global [%0], [%1], 16, %2;\n"
                 :: "r"(dst), "l"(src), "r"(sz));
}

// ---------------- kin mean ----------------
__global__ __launch_bounds__(256) void kin_mean_kernel(const float* __restrict__ kin_in,
                                                       float* __restrict__ kin_out) {
    int b = blockIdx.x;
    const float* base = kin_in + ((size_t)b * L_KIN_ + 1) * D_SEQ_;
    for (int i = threadIdx.x; i < D_SEQ_ / 4; i += blockDim.x) {
        float4 acc = make_float4(0.f, 0.f, 0.f, 0.f);
        #pragma unroll 4
        for (int r = 0; r < L_KIN_ - 1; ++r) {
            float4 v = *(const float4*)(base + (size_t)r * D_SEQ_ + i * 4);
            acc.x += v.x; acc.y += v.y; acc.z += v.z; acc.w += v.w;
        }
        const float inv = 1.f / 127.f;
        *(float4*)(kin_out + (size_t)b * D_SEQ_ + i * 4) =
            make_float4(acc.x * inv, acc.y * inv, acc.z * inv, acc.w * inv);
    }
}

// ---------------- build gfeat ----------------
__global__ __launch_bounds__(256) void build_gfeat_kernel(
    const float* __restrict__ sub, const float* __restrict__ n2,
    const float* __restrict__ phos, const int* __restrict__ position,
    float* __restrict__ X, float* __restrict__ node_feature) {
    int b = blockIdx.x, k = blockIdx.y;
    size_t m = (size_t)b * K_ + k;
    const float* src1 = sub + ((size_t)b * L_SUB_ + 1 + k) * D_SEQ_;
    float* dst = X + m * EMB_;
    float* nf  = node_feature + m * D_SEQ_;
    bool mid = (k == K_ / 2);
    for (int i = threadIdx.x; i < D_SEQ_ / 4; i += blockDim.x) {
        float4 v = *(const float4*)(src1 + i * 4);
        *(float4*)(nf + i * 4) = v;
        if (mid) {
            float4 p = *(const float4*)(phos + i * 4);
            v.x += p.x; v.y += p.y; v.z += p.z; v.w += p.w;
        }
        *(float4*)(dst + i * 4) = v;
    }
    int row = position[b] + k - K_ / 2;
    bool ok = (row >= 0 && row < L_STR_);
    const float* src2 = n2 + ((size_t)b * L_STR_ + (ok ? row : 0)) * D_STR_;
    for (int i = threadIdx.x; i < D_STR_ / 4; i += blockDim.x) {
        float4 v = make_float4(0.f, 0.f, 0.f, 0.f);
        if (ok) v = *(const float4*)(src2 + i * 4);
        if (mid) {
            float4 p = *(const float4*)(phos + D_SEQ_ + i * 4);
            v.x += p.x; v.y += p.y; v.z += p.z; v.w += p.w;
        }
        *(float4*)(dst + D_SEQ_ + i * 4) = v;
    }
}

// ---------------- column statistics ----------------
__global__ __launch_bounds__(256) void colstats_partial(
    const float* __restrict__ X, float* __restrict__ psum, float* __restrict__ psq,
    int ncols, int rows_per_chunk) {
    int col = blockIdx.x * blockDim.x + threadIdx.x;
    if (col >= ncols) return;
    int r0 = blockIdx.y * rows_per_chunk;
    float s = 0.f, q = 0.f;
    const float* p = X + (size_t)r0 * ncols + col;
    #pragma unroll 4
    for (int r = 0; r < rows_per_chunk; ++r, p += ncols) {
        float v = *p;
        s += v; q += v * v;
    }
    psum[blockIdx.y * ncols + col] = s;
    psq [blockIdx.y * ncols + col] = q;
}

__global__ __launch_bounds__(256) void finalize_stats(
    const float* __restrict__ psum, const float* __restrict__ psq, int ncols,
    const float* __restrict__ gA, const float* __restrict__ bA,
    const float* __restrict__ gB, const float* __restrict__ bB,
    float* __restrict__ sA, float* __restrict__ tA,
    float* __restrict__ sB, float* __restrict__ tB) {
    int col = blockIdx.x * blockDim.x + threadIdx.x;
    if (col >= ncols) return;
    float s = 0.f, q = 0.f;
    for (int c = 0; c < NCHUNK_; ++c) {
        s += psum[c * ncols + col];
        q += psq [c * ncols + col];
    }
    const float inv_n = 1.f / (float)M_;
    float mean = s * inv_n;
    float var  = q * inv_n - mean * mean;
    float inv  = rsqrtf(var + 1e-5f);
    float sa = gA[col] * inv; sA[col] = sa; tA[col] = bA[col] - mean * sa;
    float sb = gB[col] * inv; sB[col] = sb; tB[col] = bB[col] - mean * sb;
}

// ---------------- tf32 round-copy (weights) ----------------
__global__ __launch_bounds__(256) void roundcopy_kernel(const float* __restrict__ in,
                                                        float* __restrict__ out, int n4) {
    int i = blockIdx.x * blockDim.x + threadIdx.x;
    if (i >= n4) return;
    float4 v = *(const float4*)(in + i * 4);
    v.x = tf32r(v.x); v.y = tf32r(v.y); v.z = tf32r(v.z); v.w = tf32r(v.w);
    *(float4*)(out + i * 4) = v;
}

// ---------------- BN transform: XA = tf32r(relu(s1*x+t1)), XB = ... ----------------
__global__ __launch_bounds__(256) void bn_transform_kernel(
    const float* __restrict__ X,
    const float* __restrict__ s1, const float* __restrict__ t1,
    const float* __restrict__ s2, const float* __restrict__ t2,
    float* __restrict__ XA, float* __restrict__ XB, int ncols, int nrows) {
    size_t i = (size_t)blockIdx.x * blockDim.x + threadIdx.x;
    size_t total4 = (size_t)nrows * ncols / 4;
    if (i >= total4) return;
    int col = (int)((i * 4) % ncols);
    float4 v  = *(const float4*)(X + i * 4);
    float4 a1 = *(const float4*)(s1 + col);
    float4 b1 = *(const float4*)(t1 + col);
    float4 a2 = *(const float4*)(s2 + col);
    float4 b2 = *(const float4*)(t2 + col);
    float4 r1, r2;
    r1.x = tf32r(fmaxf(fmaf(v.x, a1.x, b1.x), 0.f));
    r1.y = tf32r(fmaxf(fmaf(v.y, a1.y, b1.y), 0.f));
    r1.z = tf32r(fmaxf(fmaf(v.z, a1.z, b1.z), 0.f));
    r1.w = tf32r(fmaxf(fmaf(v.w, a1.w, b1.w), 0.f));
    r2.x = tf32r(fmaxf(fmaf(v.x, a2.x, b2.x), 0.f));
    r2.y = tf32r(fmaxf(fmaf(v.y, a2.y, b2.y), 0.f));
    r2.z = tf32r(fmaxf(fmaf(v.z, a2.z, b2.z), 0.f));
    r2.w = tf32r(fmaxf(fmaf(v.w, a2.w, b2.w), 0.f));
    *(float4*)(XA + i * 4) = r1;
    *(float4*)(XB + i * 4) = r2;
}

// ---------------- pure tf32 GEMM: cp.async multistage, 128x256x32 ----------------
// C = A @ W + bias ; relu_out: C = tf32r(relu(C))
__global__ __launch_bounds__(256, 1) void gemm_tf32_ms(
    const float* __restrict__ A, const float* __restrict__ W,
    const float* __restrict__ bias, float* __restrict__ C,
    int Kd, int N, int relu_out) {
    extern __shared__ float smem[];
    float* sA = smem;
    float* sB = smem + GSTAGES * GA_BUF;
    const unsigned sA_u = (unsigned)__cvta_generic_to_shared(sA);
    const unsigned sB_u = (unsigned)__cvta_generic_to_shared(sB);

    const int tid  = threadIdx.x;
    const int bm   = blockIdx.y * GBM;
    const int bn   = blockIdx.x * GBN;
    const int warp = tid >> 5, lane = tid & 31;
    const int wm = (warp & 1) << 6;     // 0,64
    const int wn = (warp >> 1) << 6;    // 0,64,128,192
    const int g  = lane >> 2, tg = lane & 3;

    const int ktiles = (Kd + GBK - 1) / GBK;

    float acc[4][8][4];
    #pragma unroll
    for (int mt = 0; mt < 4; ++mt)
        #pragma unroll
        for (int nt = 0; nt < 8; ++nt)
            #pragma unroll
            for (int i = 0; i < 4; ++i) acc[mt][nt][i] = 0.f;

    // ---- async load of one stage ----
    auto load_stage = [&](int kt, int buf) {
        const int k0 = kt * GBK;
        unsigned sab = sA_u + (unsigned)(buf * GA_BUF) * 4u;
        #pragma unroll
        for (int it = 0; it < 4; ++it) {
            int idx = tid + it * 256;
            int row = idx >> 3, seg = (idx & 7) << 2;
            int gk = k0 + seg;
            bool p = (gk < Kd);
            const float* src = A + (size_t)(bm + row) * Kd + (p ? gk : 0);
            cp16(sab + (unsigned)(row * GAS + seg) * 4u, src, p);
        }
        unsigned sbb = sB_u + (unsigned)(buf * GB_BUF) * 4u;
        #pragma unroll
        for (int it = 0; it < 8; ++it) {
            int idx = tid + it * 256;
            int row = idx >> 6, seg = (idx & 63) << 2;
            int gk = k0 + row, gc = bn + seg;
            bool p = (gk < Kd) && (gc < N);
            const float* src = W + (p ? ((size_t)gk * N + gc) : 0);
            cp16(sbb + (unsigned)(row * GBS + seg) * 4u, src, p);
        }
        asm volatile("cp.async.commit_group;\n");
    };

    auto compute = [&](int buf) {
        const float* pA = sA + buf * GA_BUF;
        const float* pB = sB + buf * GB_BUF;
        #pragma unroll
        for (int kk = 0; kk < 4; ++kk) {
            const int kb = kk << 3;
            unsigned af[4][4], bf[8][2];
            #pragma unroll
            for (int mt = 0; mt < 4; ++mt) {
                int r = wm + (mt << 4);
                af[mt][0] = __float_as_uint(pA[(r + g) * GAS + kb + tg]);
                af[mt][1] = __float_as_uint(pA[(r + g + 8) * GAS + kb + tg]);
                af[mt][2] = __float_as_uint(pA[(r + g) * GAS + kb + tg + 4]);
                af[mt][3] = __float_as_uint(pA[(r + g + 8) * GAS + kb + tg + 4]);
            }
            #pragma unroll
            for (int nt = 0; nt < 8; ++nt) {
                int c = wn + (nt << 3) + g;
                bf[nt][0] = __float_as_uint(pB[(kb + tg) * GBS + c]);
                bf[nt][1] = __float_as_uint(pB[(kb + tg + 4) * GBS + c]);
            }
            #pragma unroll
            for (int mt = 0; mt < 4; ++mt)
                #pragma unroll
                for (int nt = 0; nt < 8; ++nt)
                    mma_tf32(acc[mt][nt], af[mt], bf[nt]);
        }
    };

    // ---- prologue: fill GSTAGES-1 stages ----
    #pragma unroll
    for (int s = 0; s < GSTAGES - 1; ++s) load_stage(s, s);

    // ---- main loop: one barrier per slab ----
    for (int kt = 0; kt < ktiles; ++kt) {
        asm volatile("cp.async.wait_group %0;\n" :: "n"(GSTAGES - 2));
        __syncthreads();
        int nxt = kt + GSTAGES - 1;
        if (nxt < ktiles) load_stage(nxt, nxt % GSTAGES);
        else asm volatile("cp.async.commit_group;\n");
        compute(kt % GSTAGES);
    }

    // ---- epilogue ----
    #pragma unroll
    for (int mt = 0; mt < 4; ++mt) {
        int r = bm + wm + (mt << 4);
        #pragma unroll
        for (int nt = 0; nt < 8; ++nt) {
            int c = bn + wn + (nt << 3) + (tg << 1);
            if (c < N) {
                float b0 = bias[c], b1 = bias[c + 1];
                float v00 = acc[mt][nt][0] + b0, v01 = acc[mt][nt][1] + b1;
                float v10 = acc[mt][nt][2] + b0, v11 = acc[mt][nt][3] + b1;
                if (relu_out) {
                    v00 = tf32r(fmaxf(v00, 0.f)); v01 = tf32r(fmaxf(v01, 0.f));
                    v10 = tf32r(fmaxf(v10, 0.f)); v11 = tf32r(fmaxf(v11, 0.f));
                }
                C[(size_t)(r + g) * N + c]         = v00;
                C[(size_t)(r + g) * N + c + 1]     = v01;
                C[(size_t)(r + g + 8) * N + c]     = v10;
                C[(size_t)(r + g + 8) * N + c + 1] = v11;
            }
        }
    }
}

// ---------------- combine stage 1 -> gfeat2 ----------------
__global__ __launch_bounds__(256) void combine1_kernel(
    const float* __restrict__ F1, const float* __restrict__ F2,
    const float* __restrict__ nf, const float* __restrict__ kin,
    const float* __restrict__ a, const int* __restrict__ raw_seq,
    float* __restrict__ X2) {
    int b = blockIdx.x, k = blockIdx.y;
    size_t m = (size_t)b * K_ + k;
    float a0 = a[0], a1 = a[1];
    const float* f1 = F1 + m * D_SEQ_;
    const float* f2 = F2 + m * D_SEQ_;
    const float* g1 = nf + m * D_SEQ_;
    const float* kb = kin + (size_t)b * D_SEQ_;
    float* dst = X2 + m * EMB2_;
    for (int i = threadIdx.x; i < D_SEQ_ / 4; i += blockDim.x) {
        float4 v1 = *(const float4*)(f1 + i * 4);
        float4 v2 = *(const float4*)(f2 + i * 4);
        float4 vg = *(const float4*)(g1 + i * 4);
        float4 r;
        r.x = sigmoidf_(v1.x) * vg.x * a0 + v2.x * a1;
        r.y = sigmoidf_(v1.y) * vg.y * a0 + v2.y * a1;
        r.z = sigmoidf_(v1.z) * vg.z * a0 + v2.z * a1;
        r.w = sigmoidf_(v1.w) * vg.w * a0 + v2.w * a1;
        *(float4*)(dst + i * 4) = r;
        *(float4*)(dst + D_SEQ_ + i * 4) = *(const float4*)(kb + i * 4);
    }
    if (threadIdx.x < 4) {
        int sid = raw_seq[m];
        dst[2 * D_SEQ_ + threadIdx.x] = c_props[sid * 4 + threadIdx.x];
    }
}

// ---------------- final combine + K-reduce ----------------
__global__ __launch_bounds__(256) void final_kernel(
    const float* __restrict__ G1, const float* __restrict__ G2,
    const float* __restrict__ X2, const float* __restrict__ a2,
    float* __restrict__ out) {
    int b = blockIdx.x;
    float s0 = a2[0], s1 = a2[1];
    for (int i = threadIdx.x; i < D_SEQ_ / 4; i += blockDim.x) {
        float4 acc = make_float4(0.f, 0.f, 0.f, 0.f);
        for (int k = 0; k < K_; ++k) {
            size_t m = (size_t)b * K_ + k;
            float4 f1 = *(const float4*)(G1 + m * D_SEQ_ + i * 4);
            float4 f2 = *(const float4*)(G2 + m * D_SEQ_ + i * 4);
            float4 gn = *(const float4*)(X2 + m * EMB2_ + i * 4);
            acc.x += sigmoidf_(f1.x) * gn.x * s0 + f2.x * s1;
            acc.y += sigmoidf_(f1.y) * gn.y * s0 + f2.y * s1;
            acc.z += sigmoidf_(f1.z) * gn.z * s0 + f2.z * s1;
            acc.w += sigmoidf_(f1.w) * gn.w * s0 + f2.w * s1;
        }
        *(float4*)(out + (size_t)b * D_SEQ_ + i * 4) = acc;
    }
}

// ---------------- launch ----------------
extern "C" void kernel_launch(void* const* d_in, const int* in_sizes, int n_in,
                              void* d_out, int out_size) {
    const float* kin_in   = (const float*)d_in[0];
    const float* sub      = (const float*)d_in[1];
    const float* n2       = (const float*)d_in[2];
    const float* a        = (const float*)d_in[4];
    const float* a2       = (const float*)d_in[5];
    const float* phos     = (const float*)d_in[6];
    const float* g1_gamma = (const float*)d_in[7];
    const float* g1_beta  = (const float*)d_in[8];
    const float* g1_W     = (const float*)d_in[9];
    const float* g1_b     = (const float*)d_in[10];
    const float* r1_gamma = (const float*)d_in[11];
    const float* r1_beta  = (const float*)d_in[12];
    const float* r1_W1    = (const float*)d_in[13];
    const float* r1_b1    = (const float*)d_in[14];
    const float* r1_W2    = (const float*)d_in[15];
    const float* r1_b2    = (const float*)d_in[16];
    const float* g2_gamma = (const float*)d_in[17];
    const float* g2_beta  = (const float*)d_in[18];
    const float* g2_W     = (const float*)d_in[19];
    const float* g2_b     = (const float*)d_in[20];
    const float* r2_gamma = (const float*)d_in[21];
    const float* r2_beta  = (const float*)d_in[22];
    const float* r2_W1    = (const float*)d_in[23];
    const float* r2_b1    = (const float*)d_in[24];
    const float* r2_W2    = (const float*)d_in[25];
    const float* r2_b2    = (const float*)d_in[26];
    const int*   position = (const int*)d_in[27];
    const int*   raw_seq  = (const int*)d_in[28];

    float* out = (float*)d_out;
    float* graph_feature = out;
    float* node_feature  = out + (size_t)B_ * D_SEQ_;

    float *X, *Y, *XA, *XB, *P1, *P2, *Wr, *kin, *psum, *psq, *ss;
    cudaGetSymbolAddress((void**)&X,    g_X);
    cudaGetSymbolAddress((void**)&Y,    g_Y);
    cudaGetSymbolAddress((void**)&XA,   g_XA);
    cudaGetSymbolAddress((void**)&XB,   g_XB);
    cudaGetSymbolAddress((void**)&P1,   g_P1);
    cudaGetSymbolAddress((void**)&P2,   g_P2);
    cudaGetSymbolAddress((void**)&Wr,   g_Wr);
    cudaGetSymbolAddress((void**)&kin,  g_kin);
    cudaGetSymbolAddress((void**)&psum, g_psum);
    cudaGetSymbolAddress((void**)&psq,  g_psq);
    cudaGetSymbolAddress((void**)&ss,   g_ss);

    const int smem_bytes = GSMEM_FLOATS * (int)sizeof(float);   // 155136
    cudaFuncSetAttribute(gemm_tf32_ms,
                         cudaFuncAttributeMaxDynamicSharedMemorySize, smem_bytes);

    float* s_g1 = ss + 0 * EMB2_;  float* t_g1 = ss + 1 * EMB2_;
    float* s_r1 = ss + 2 * EMB2_;  float* t_r1 = ss + 3 * EMB2_;
    float* s_g2 = ss + 4 * EMB2_;  float* t_g2 = ss + 5 * EMB2_;
    float* s_r2 = ss + 6 * EMB2_;  float* t_r2 = ss + 7 * EMB2_;

    // pre-rounded weight offsets
    const int n_g1W  = EMB_  * D_SEQ_;   // 2293760
    const int n_r1W1 = EMB_  * EMB_;     // 3211264
    const int n_r1W2 = EMB_  * D_SEQ_;
    const int n_g2W  = EMB2_ * D_SEQ_;   // 3281920
    const int n_r2W1 = EMB2_ * EMB2_;    // 6574096
    float* W_g1  = Wr;
    float* W_r11 = W_g1  + n_g1W;
    float* W_r12 = W_r11 + n_r1W1;
    float* W_g2  = W_r12 + n_r1W2;
    float* W_r21 = W_g2  + n_g2W;
    float* W_r22 = W_r21 + n_r2W1;

    // 0. round weights to tf32 (RNA) once per launch
    auto rc = [&](const float* src, float* dst, int n) {
        roundcopy_kernel<<<(n / 4 + 255) / 256, 256>>>(src, dst, n / 4);
    };
    rc(g1_W,  W_g1,  n_g1W);
    rc(r1_W1, W_r11, n_r1W1);
    rc(r1_W2, W_r12, n_r1W2);
    rc(g2_W,  W_g2,  n_g2W);
    rc(r2_W1, W_r21, n_r2W1);
    rc(r2_W2, W_r22, EMB2_ * D_SEQ_);

    // 1. kin mean
    kin_mean_kernel<<<B_, 256>>>(kin_in, kin);

    // 2. build gfeat
    build_gfeat_kernel<<<dim3(B_, K_), 256>>>(sub, n2, phos, position, X, node_feature);

    // 3. BN stats stage 1
    colstats_partial<<<dim3((EMB_ + 255) / 256, NCHUNK_), 256>>>(X, psum, psq, EMB_, M_ / NCHUNK_);
    finalize_stats<<<(EMB_ + 255) / 256, 256>>>(psum, psq, EMB_,
        g1_gamma, g1_beta, r1_gamma, r1_beta, s_g1, t_g1, s_r1, t_r1);

    // 4. transforms
    {
        size_t total4 = (size_t)M_ * EMB_ / 4;
        bn_transform_kernel<<<(int)((total4 + 255) / 256), 256>>>(
            X, s_g1, t_g1, s_r1, t_r1, XA, XB, EMB_, M_);
    }

    // 5-7. stage-1 GEMMs (pure)
    gemm_tf32_ms<<<dim3(D_SEQ_ / GBN, M_ / GBM), 256, smem_bytes>>>(XA, W_g1,  g1_b,  P1, EMB_, D_SEQ_, 0);
    gemm_tf32_ms<<<dim3(EMB_  / GBN, M_ / GBM), 256, smem_bytes>>>(XB, W_r11, r1_b1, Y,  EMB_, EMB_,  1);
    gemm_tf32_ms<<<dim3(D_SEQ_ / GBN, M_ / GBM), 256, smem_bytes>>>(Y,  W_r12, r1_b2, P2, EMB_, D_SEQ_, 0);

    // 8. combine -> gfeat2
    combine1_kernel<<<dim3(B_, K_), 256>>>(P1, P2, node_feature, kin, a, raw_seq, X);

    // 9. BN stats stage 2
    colstats_partial<<<dim3((EMB2_ + 255) / 256, NCHUNK_), 256>>>(X, psum, psq, EMB2_, M_ / NCHUNK_);
    finalize_stats<<<(EMB2_ + 255) / 256, 256>>>(psum, psq, EMB2_,
        g2_gamma, g2_beta, r2_gamma, r2_beta, s_g2, t_g2, s_r2, t_r2);

    // 10. transforms stage 2
    {
        size_t total4 = (size_t)M_ * EMB2_ / 4;
        bn_transform_kernel<<<(int)((total4 + 255) / 256), 256>>>(
            X, s_g2, t_g2, s_r2, t_r2, XA, XB, EMB2_, M_);
    }

    // 11-13. stage-2 GEMMs
    gemm_tf32_ms<<<dim3(D_SEQ_ / GBN, M_ / GBM), 256, smem_bytes>>>(XA, W_g2,  g2_b,  P1, EMB2_, D_SEQ_, 0);
    gemm_tf32_ms<<<dim3((EMB2_ + GBN - 1) / GBN, M_ / GBM), 256, smem_bytes>>>(XB, W_r21, r2_b1, Y, EMB2_, EMB2_, 1);
    gemm_tf32_ms<<<dim3(D_SEQ_ / GBN, M_ / GBM), 256, smem_bytes>>>(Y,  W_r22, r2_b2, P2, EMB2_, D_SEQ_, 0);

    // 14. final combine + K-reduce
    final_kernel<<<B_, 256>>>(P1, P2, X, a2, graph_feature);
}

// round 7
// speedup vs baseline: 1.0112x; 1.0112x over previous
#include <cuda_runtime.h>
#include <cuda_bf16.h>
#include <cstdint>

#define B_      1024
#define K_      11
#define L_KIN_  128
#define L_SUB_  64
#define L_STR_  128
#define D_SEQ_  1280
#define D_STR_  512
#define EMB_    1792
#define EMB2_   2564
#define M_      (B_ * K_)
#define NCHUNK_ 44
#define KP1     1792
#define KP2     2592
#define NP_R21  2816

#define GBM 128
#define GBN 256
#define GSTAGES 3
#define AS 40
#define GA_BUF (GBM * AS)           // 5120 floats
#define GB_BUF (GBN * AS)           // 10240 floats
#define GSMEM_BYTES (GSTAGES * (GA_BUF + GB_BUF) * 4)   // 184320

__device__ float g_X [(size_t)M_ * EMB2_];
__device__ float g_Y [(size_t)M_ * KP2];
__device__ float g_XA[(size_t)M_ * KP2];
__device__ float g_XB[(size_t)M_ * KP2];
__device__ float g_P1[(size_t)M_ * D_SEQ_];
__device__ float g_P2[(size_t)M_ * D_SEQ_];
__device__ float g_Wt[21733376];
__device__ float g_kin[(size_t)B_ * D_SEQ_];
__device__ float g_psum[NCHUNK_ * EMB2_];
__device__ float g_psq [NCHUNK_ * EMB2_];
__device__ float g_ss  [8 * EMB2_];

__constant__ float c_props[21 * 4] = {
    0,0,0,0,  1,0,0,0,  0,0,0,0,  0,0,0,0,  1,0,0,0,  0,0,0,0,  0,0,0,0,
    1,0,0,0,  1,0,0,0,  0,0,0,0,  0,0,1,0,  0,0,0,0,  0,0,0,1,  0,0,1,0,
    1,0,0,0,  0,0,0,1,  0,1,0,0,  0,0,0,1,  0,1,0,0,  0,1,0,0,  0,0,0,0
};

__device__ __forceinline__ float tf32r(float x) {
    unsigned u;
    asm("cvt.rna.tf32.f32 %0, %1;" : "=r"(u) : "f"(x));
    return __uint_as_float(u);
}
__device__ __forceinline__ float sigmoidf_(float x) { return 1.f / (1.f + expf(-x)); }
__device__ __forceinline__ int pk_(int k) {          // pairing permutation within k-groups of 8
    return (k & ~7) | (((k & 3) << 1) | ((k >> 2) & 1));
}
__device__ __forceinline__ void mma_tf32(float* d, const unsigned* a, const unsigned* b) {
    asm volatile(
        "mma.sync.aligned.m16n8k8.row.col.f32.tf32.tf32.f32 "
        "{%0,%1,%2,%3}, {%4,%5,%6,%7}, {%8,%9}, {%0,%1,%2,%3};\n"
        : "+f"(d[0]), "+f"(d[1]), "+f"(d[2]), "+f"(d[3])
        : "r"(a[0]), "r"(a[1]), "r"(a[2]), "r"(a[3]), "r"(b[0]), "r"(b[1]));
}
__device__ __forceinline__ void cp16u(unsigned dst, const void* src) {
    asm volatile("cp.async.cg.shared.global [%0], [%1], 16;\n" :: "r"(dst), "l"(src));
}

// ---- fused transpose+round+pair for all 6 weights: Wt[n][pk(k)] = tf32r(W[k][n]) ----
__global__ __launch_bounds__(256) void transpose_all(
    const float* __restrict__ W0, const float* __restrict__ W1, const float* __restrict__ W2,
    const float* __restrict__ W3, const float* __restrict__ W4, const float* __restrict__ W5,
    float* __restrict__ D0, float* __restrict__ D1, float* __restrict__ D2,
    float* __restrict__ D3, float* __restrict__ D4, float* __restrict__ D5) {
    __shared__ float t[32][33];
    int bx = blockIdx.x;
    const float* W; float* D; int K, N, KP, kb, blk;
    if      (bx < 2240)  { W=W0; D=D0; K=EMB_;  N=1280; KP=KP1; kb=56; blk=bx; }
    else if (bx < 5376)  { W=W1; D=D1; K=EMB_;  N=1792; KP=KP1; kb=56; blk=bx-2240; }
    else if (bx < 7616)  { W=W2; D=D2; K=EMB_;  N=1280; KP=KP1; kb=56; blk=bx-5376; }
    else if (bx < 10856) { W=W3; D=D3; K=EMB2_; N=1280; KP=KP2; kb=81; blk=bx-7616; }
    else if (bx < 17984) { W=W4; D=D4; K=EMB2_; N=EMB2_; KP=KP2; kb=81; blk=bx-10856; }
    else                 { W=W5; D=D5; K=EMB2_; N=1280; KP=KP2; kb=81; blk=bx-17984; }
    int k0 = (blk % kb) * 32, n0 = (blk / kb) * 32;
    int tx = threadIdx.x & 31, ty = threadIdx.x >> 5;
    #pragma unroll
    for (int j = 0; j < 4; ++j) {
        int k = k0 + ty + j * 8, n = n0 + tx;
        t[ty + j * 8][tx] = (k < K && n < N) ? W[(size_t)k * N + n] : 0.f;
    }
    __syncthreads();
    #pragma unroll
    for (int j = 0; j < 4; ++j) {
        int n = n0 + ty + j * 8, k = k0 + tx;
        D[(size_t)n * KP + pk_(k)] = tf32r(t[tx][ty + j * 8]);
    }
}

// ---- fused kin-mean + build-gfeat ----
__global__ __launch_bounds__(256) void kin_build_kernel(
    const float* __restrict__ kin_in, const float* __restrict__ sub,
    const float* __restrict__ n2, const float* __restrict__ phos,
    const int* __restrict__ position,
    float* __restrict__ kin_out, float* __restrict__ X, float* __restrict__ node_feature) {
    int b = blockIdx.x, k = blockIdx.y;
    if (k == K_) {   // kin mean
        const float* base = kin_in + ((size_t)b * L_KIN_ + 1) * D_SEQ_;
        for (int i = threadIdx.x; i < D_SEQ_ / 4; i += blockDim.x) {
            float4 acc = make_float4(0.f, 0.f, 0.f, 0.f);
            #pragma unroll 4
            for (int r = 0; r < L_KIN_ - 1; ++r) {
                float4 v = *(const float4*)(base + (size_t)r * D_SEQ_ + i * 4);
                acc.x += v.x; acc.y += v.y; acc.z += v.z; acc.w += v.w;
            }
            const float inv = 1.f / 127.f;
            *(float4*)(kin_out + (size_t)b * D_SEQ_ + i * 4) =
                make_float4(acc.x * inv, acc.y * inv, acc.z * inv, acc.w * inv);
        }
        return;
    }
    size_t m = (size_t)b * K_ + k;
    const float* src1 = sub + ((size_t)b * L_SUB_ + 1 + k) * D_SEQ_;
    float* dst = X + m * EMB_;
    float* nf  = node_feature + m * D_SEQ_;
    bool mid = (k == K_ / 2);
    for (int i = threadIdx.x; i < D_SEQ_ / 4; i += blockDim.x) {
        float4 v = *(const float4*)(src1 + i * 4);
        *(float4*)(nf + i * 4) = v;
        if (mid) {
            float4 p = *(const float4*)(phos + i * 4);
            v.x += p.x; v.y += p.y; v.z += p.z; v.w += p.w;
        }
        *(float4*)(dst + i * 4) = v;
    }
    int row = position[b] + k - K_ / 2;
    bool ok = (row >= 0 && row < L_STR_);
    const float* src2 = n2 + ((size_t)b * L_STR_ + (ok ? row : 0)) * D_STR_;
    for (int i = threadIdx.x; i < D_STR_ / 4; i += blockDim.x) {
        float4 v = make_float4(0.f, 0.f, 0.f, 0.f);
        if (ok) v = *(const float4*)(src2 + i * 4);
        if (mid) {
            float4 p = *(const float4*)(phos + D_SEQ_ + i * 4);
            v.x += p.x; v.y += p.y; v.z += p.z; v.w += p.w;
        }
        *(float4*)(dst + D_SEQ_ + i * 4) = v;
    }
}

__global__ __launch_bounds__(256) void colstats_partial(
    const float* __restrict__ X, float* __restrict__ psum, float* __restrict__ psq,
    int ncols, int rows_per_chunk) {
    int col = blockIdx.x * blockDim.x + threadIdx.x;
    if (col >= ncols) return;
    int r0 = blockIdx.y * rows_per_chunk;
    float s = 0.f, q = 0.f;
    const float* p = X + (size_t)r0 * ncols + col;
    #pragma unroll 4
    for (int r = 0; r < rows_per_chunk; ++r, p += ncols) {
        float v = *p;
        s += v; q += v * v;
    }
    psum[blockIdx.y * ncols + col] = s;
    psq [blockIdx.y * ncols + col] = q;
}

__global__ __launch_bounds__(256) void finalize_stats(
    const float* __restrict__ psum, const float* __restrict__ psq, int ncols,
    const float* __restrict__ gA, const float* __restrict__ bA,
    const float* __restrict__ gB, const float* __restrict__ bB,
    float* __restrict__ sA, float* __restrict__ tA,
    float* __restrict__ sB, float* __restrict__ tB) {
    int col = blockIdx.x * blockDim.x + threadIdx.x;
    if (col >= ncols) return;
    float s = 0.f, q = 0.f;
    for (int c = 0; c < NCHUNK_; ++c) {
        s += psum[c * ncols + col];
        q += psq [c * ncols + col];
    }
    const float inv_n = 1.f / (float)M_;
    float mean = s * inv_n;
    float var  = q * inv_n - mean * mean;
    float inv  = rsqrtf(var + 1e-5f);
    float sa = gA[col] * inv; sA[col] = sa; tA[col] = bA[col] - mean * sa;
    float sb = gB[col] * inv; sB[col] = sb; tB[col] = bB[col] - mean * sb;
}

// ---- BN transform with k-pairing: XA/XB[row][grp*8 + c*2 + {0,1}] = bn(X[row][grp*8+c / +c+4]) ----
__global__ __launch_bounds__(256) void bn_transform_kernel(
    const float* __restrict__ X,
    const float* __restrict__ s1, const float* __restrict__ t1,
    const float* __restrict__ s2, const float* __restrict__ t2,
    float* __restrict__ XA, float* __restrict__ XB, int ncols, int ldo, int nj) {
    int j = blockIdx.x * blockDim.x + threadIdx.x;
    if (j >= nj) return;
    int row = blockIdx.y;
    int grp = j >> 2, c = j & 3;
    int c1 = grp * 8 + c, c2 = c1 + 4;
    const float* xr = X + (size_t)row * ncols;
    float r1a = 0.f, r1b = 0.f, r2a = 0.f, r2b = 0.f;
    if (c1 < ncols) {
        float v = xr[c1];
        r1a = tf32r(fmaxf(fmaf(v, s1[c1], t1[c1]), 0.f));
        r2a = tf32r(fmaxf(fmaf(v, s2[c1], t2[c1]), 0.f));
    }
    if (c2 < ncols) {
        float v = xr[c2];
        r1b = tf32r(fmaxf(fmaf(v, s1[c2], t1[c2]), 0.f));
        r2b = tf32r(fmaxf(fmaf(v, s2[c2], t2[c2]), 0.f));
    }
    size_t o = (size_t)row * ldo + grp * 8 + c * 2;
    *(float2*)(XA + o) = make_float2(r1a, r1b);
    *(float2*)(XB + o) = make_float2(r2a, r2b);
}

// ---- tf32 GEMM, paired-k smem layout, LDS.64 fragments, cp.async 3-stage ----
// A[M][lda] paired-k; Wt[n][lda] paired-k. C = A@W^T + bias.
// flags&1: relu+tf32r output AND paired-k output layout (for Y feeding next GEMM).
__global__ __launch_bounds__(256, 1) void gemm_tf32p(
    const float* __restrict__ A, const float* __restrict__ Wt,
    const float* __restrict__ bias, float* __restrict__ C,
    int lda, int ktiles, int Nout, int Nzero, int ldc, int flags) {
    extern __shared__ float smem[];
    float* sA = smem;
    float* sB = smem + GSTAGES * GA_BUF;
    const unsigned sA_u = (unsigned)__cvta_generic_to_shared(sA);
    const unsigned sB_u = (unsigned)__cvta_generic_to_shared(sB);

    const int tid  = threadIdx.x;
    const int bm   = blockIdx.y * GBM;
    const int bn   = blockIdx.x * GBN;
    const int warp = tid >> 5, lane = tid & 31;
    const int wm = (warp & 1) << 6;
    const int wn = (warp >> 1) << 6;
    const int g  = lane >> 2, tg = lane & 3;

    float acc[4][8][4];
    #pragma unroll
    for (int mt = 0; mt < 4; ++mt)
        #pragma unroll
        for (int nt = 0; nt < 8; ++nt)
            #pragma unroll
            for (int i = 0; i < 4; ++i) acc[mt][nt][i] = 0.f;

    auto load_stage = [&](int kt, int buf) {
        const int k0 = kt * 32;
        unsigned sab = sA_u + (unsigned)(buf * GA_BUF) * 4u;
        #pragma unroll
        for (int it = 0; it < 4; ++it) {
            int idx = tid + it * 256;
            int row = idx >> 3, seg = idx & 7;
            cp16u(sab + (unsigned)(row * AS + seg * 4) * 4u,
                  A + (size_t)(bm + row) * lda + k0 + seg * 4);
        }
        unsigned sbb = sB_u + (unsigned)(buf * GB_BUF) * 4u;
        #pragma unroll
        for (int it = 0; it < 8; ++it) {
            int idx = tid + it * 256;
            int row = idx >> 3, seg = idx & 7;
            cp16u(sbb + (unsigned)(row * AS + seg * 4) * 4u,
                  Wt + (size_t)(bn + row) * lda + k0 + seg * 4);
        }
        asm volatile("cp.async.commit_group;\n");
    };

    auto compute = [&](int buf) {
        const float* pA = sA + buf * GA_BUF;
        const float* pB = sB + buf * GB_BUF;
        #pragma unroll
        for (int kk = 0; kk < 4; ++kk) {
            const int ko = kk * 8 + tg * 2;
            unsigned af[4][4], bf[8][2];
            #pragma unroll
            for (int mt = 0; mt < 4; ++mt) {
                int r = wm + (mt << 4);
                float2 lo = *(const float2*)&pA[(r + g) * AS + ko];
                float2 hi = *(const float2*)&pA[(r + g + 8) * AS + ko];
                af[mt][0] = __float_as_uint(lo.x);
                af[mt][2] = __float_as_uint(lo.y);
                af[mt][1] = __float_as_uint(hi.x);
                af[mt][3] = __float_as_uint(hi.y);
            }
            #pragma unroll
            for (int nt = 0; nt < 8; ++nt) {
                int c = wn + (nt << 3) + g;
                float2 bv = *(const float2*)&pB[c * AS + ko];
                bf[nt][0] = __float_as_uint(bv.x);
                bf[nt][1] = __float_as_uint(bv.y);
            }
            #pragma unroll
            for (int mt = 0; mt < 4; ++mt)
                #pragma unroll
                for (int nt = 0; nt < 8; ++nt)
                    mma_tf32(acc[mt][nt], af[mt], bf[nt]);
        }
    };

    #pragma unroll
    for (int s = 0; s < GSTAGES - 1; ++s) load_stage(s, s);

    for (int kt = 0; kt < ktiles; ++kt) {
        asm volatile("cp.async.wait_group %0;\n" :: "n"(GSTAGES - 2));
        __syncthreads();
        int nxt = kt + GSTAGES - 1;
        if (nxt < ktiles) load_stage(nxt, nxt % GSTAGES);
        else asm volatile("cp.async.commit_group;\n");
        compute(kt % GSTAGES);
    }

    const int relu_pair = flags & 1;
    #pragma unroll
    for (int mt = 0; mt < 4; ++mt) {
        int r = bm + wm + (mt << 4);
        #pragma unroll
        for (int nt = 0; nt < 8; ++nt) {
            int c = bn + wn + (nt << 3) + (tg << 1);
            #pragma unroll
            for (int half = 0; half < 2; ++half) {
                int cc = c + half;
                if (cc >= Nzero) continue;
                float v0 = 0.f, v1 = 0.f;
                if (cc < Nout) {
                    float bb = bias[cc];
                    v0 = acc[mt][nt][half]     + bb;
                    v1 = acc[mt][nt][half + 2] + bb;
                    if (relu_pair) {
                        v0 = tf32r(fmaxf(v0, 0.f));
                        v1 = tf32r(fmaxf(v1, 0.f));
                    }
                }
                int oc = relu_pair ? ((cc & ~7) | (((cc & 3) << 1) | ((cc >> 2) & 1))) : cc;
                C[(size_t)(r + g) * ldc + oc]     = v0;
                C[(size_t)(r + g + 8) * ldc + oc] = v1;
            }
        }
    }
}

__global__ __launch_bounds__(256) void combine1_kernel(
    const float* __restrict__ F1, const float* __restrict__ F2,
    const float* __restrict__ nf, const float* __restrict__ kin,
    const float* __restrict__ a, const int* __restrict__ raw_seq,
    float* __restrict__ X2) {
    int b = blockIdx.x, k = blockIdx.y;
    size_t m = (size_t)b * K_ + k;
    float a0 = a[0], a1 = a[1];
    const float* f1 = F1 + m * D_SEQ_;
    const float* f2 = F2 + m * D_SEQ_;
    const float* g1 = nf + m * D_SEQ_;
    const float* kb = kin + (size_t)b * D_SEQ_;
    float* dst = X2 + m * EMB2_;
    for (int i = threadIdx.x; i < D_SEQ_ / 4; i += blockDim.x) {
        float4 v1 = *(const float4*)(f1 + i * 4);
        float4 v2 = *(const float4*)(f2 + i * 4);
        float4 vg = *(const float4*)(g1 + i * 4);
        float4 r;
        r.x = sigmoidf_(v1.x) * vg.x * a0 + v2.x * a1;
        r.y = sigmoidf_(v1.y) * vg.y * a0 + v2.y * a1;
        r.z = sigmoidf_(v1.z) * vg.z * a0 + v2.z * a1;
        r.w = sigmoidf_(v1.w) * vg.w * a0 + v2.w * a1;
        *(float4*)(dst + i * 4) = r;
        *(float4*)(dst + D_SEQ_ + i * 4) = *(const float4*)(kb + i * 4);
    }
    if (threadIdx.x < 4) {
        int sid = raw_seq[m];
        dst[2 * D_SEQ_ + threadIdx.x] = c_props[sid * 4 + threadIdx.x];
    }
}

__global__ __launch_bounds__(256) void final_kernel(
    const float* __restrict__ G1, const float* __restrict__ G2,
    const float* __restrict__ X2, const float* __restrict__ a2,
    float* __restrict__ out) {
    int b = blockIdx.x;
    float s0 = a2[0], s1 = a2[1];
    for (int i = threadIdx.x; i < D_SEQ_ / 4; i += blockDim.x) {
        float4 acc = make_float4(0.f, 0.f, 0.f, 0.f);
        for (int k = 0; k < K_; ++k) {
            size_t m = (size_t)b * K_ + k;
            float4 f1 = *(const float4*)(G1 + m * D_SEQ_ + i * 4);
            float4 f2 = *(const float4*)(G2 + m * D_SEQ_ + i * 4);
            float4 gn = *(const float4*)(X2 + m * EMB2_ + i * 4);
            acc.x += sigmoidf_(f1.x) * gn.x * s0 + f2.x * s1;
            acc.y += sigmoidf_(f1.y) * gn.y * s0 + f2.y * s1;
            acc.z += sigmoidf_(f1.z) * gn.z * s0 + f2.z * s1;
            acc.w += sigmoidf_(f1.w) * gn.w * s0 + f2.w * s1;
        }
        *(float4*)(out + (size_t)b * D_SEQ_ + i * 4) = acc;
    }
}

extern "C" void kernel_launch(void* const* d_in, const int* in_sizes, int n_in,
                              void* d_out, int out_size) {
    const float* kin_in   = (const float*)d_in[0];
    const float* sub      = (const float*)d_in[1];
    const float* n2       = (const float*)d_in[2];
    const float* a        = (const float*)d_in[4];
    const float* a2       = (const float*)d_in[5];
    const float* phos     = (const float*)d_in[6];
    const float* g1_gamma = (const float*)d_in[7];
    const float* g1_beta  = (const float*)d_in[8];
    const float* g1_W     = (const float*)d_in[9];
    const float* g1_b     = (const float*)d_in[10];
    const float* r1_gamma = (const float*)d_in[11];
    const float* r1_beta  = (const float*)d_in[12];
    const float* r1_W1    = (const float*)d_in[13];
    const float* r1_b1    = (const float*)d_in[14];
    const float* r1_W2    = (const float*)d_in[15];
    const float* r1_b2    = (const float*)d_in[16];
    const float* g2_gamma = (const float*)d_in[17];
    const float* g2_beta  = (const float*)d_in[18];
    const float* g2_W     = (const float*)d_in[19];
    const float* g2_b     = (const float*)d_in[20];
    const float* r2_gamma = (const float*)d_in[21];
    const float* r2_beta  = (const float*)d_in[22];
    const float* r2_W1    = (const float*)d_in[23];
    const float* r2_b1    = (const float*)d_in[24];
    const float* r2_W2    = (const float*)d_in[25];
    const float* r2_b2    = (const float*)d_in[26];
    const int*   position = (const int*)d_in[27];
    const int*   raw_seq  = (const int*)d_in[28];

    float* out = (float*)d_out;
    float* graph_feature = out;
    float* node_feature  = out + (size_t)B_ * D_SEQ_;

    float *X, *Y, *XA, *XB, *P1, *P2, *Wt, *kin, *psum, *psq, *ss;
    cudaGetSymbolAddress((void**)&X,    g_X);
    cudaGetSymbolAddress((void**)&Y,    g_Y);
    cudaGetSymbolAddress((void**)&XA,   g_XA);
    cudaGetSymbolAddress((void**)&XB,   g_XB);
    cudaGetSymbolAddress((void**)&P1,   g_P1);
    cudaGetSymbolAddress((void**)&P2,   g_P2);
    cudaGetSymbolAddress((void**)&Wt,   g_Wt);
    cudaGetSymbolAddress((void**)&kin,  g_kin);
    cudaGetSymbolAddress((void**)&psum, g_psum);
    cudaGetSymbolAddress((void**)&psq,  g_psq);
    cudaGetSymbolAddress((void**)&ss,   g_ss);

    cudaFuncSetAttribute(gemm_tf32p, cudaFuncAttributeMaxDynamicSharedMemorySize, GSMEM_BYTES);

    float* s_g1 = ss + 0 * EMB2_;  float* t_g1 = ss + 1 * EMB2_;
    float* s_r1 = ss + 2 * EMB2_;  float* t_r1 = ss + 3 * EMB2_;
    float* s_g2 = ss + 4 * EMB2_;  float* t_g2 = ss + 5 * EMB2_;
    float* s_r2 = ss + 6 * EMB2_;  float* t_r2 = ss + 7 * EMB2_;

    float* Wt_g1  = Wt;
    float* Wt_r11 = Wt_g1  + (size_t)1280 * KP1;
    float* Wt_r12 = Wt_r11 + (size_t)1792 * KP1;
    float* Wt_g2  = Wt_r12 + (size_t)1280 * KP1;
    float* Wt_r21 = Wt_g2  + (size_t)1280 * KP2;
    float* Wt_r22 = Wt_r21 + (size_t)NP_R21 * KP2;

    // launch 0: all weight transposes (paired-k, tf32-rounded, zero-padded)
    transpose_all<<<21224, 256>>>(g1_W, r1_W1, r1_W2, g2_W, r2_W1, r2_W2,
                                  Wt_g1, Wt_r11, Wt_r12, Wt_g2, Wt_r21, Wt_r22);
    // launch 1: kin mean + gfeat build
    kin_build_kernel<<<dim3(B_, K_ + 1), 256>>>(kin_in, sub, n2, phos, position,
                                                kin, X, node_feature);
    // launches 2-4: stats + transform
    colstats_partial<<<dim3((EMB_ + 255) / 256, NCHUNK_), 256>>>(X, psum, psq, EMB_, M_ / NCHUNK_);
    finalize_stats<<<(EMB_ + 255) / 256, 256>>>(psum, psq, EMB_,
        g1_gamma, g1_beta, r1_gamma, r1_beta, s_g1, t_g1, s_r1, t_r1);
    bn_transform_kernel<<<dim3((KP1 / 2 + 255) / 256, M_), 256>>>(
        X, s_g1, t_g1, s_r1, t_r1, XA, XB, EMB_, KP1, KP1 / 2);

    // launches 5-7: stage-1 GEMMs (launch 5 = ncu capture slot)
    gemm_tf32p<<<dim3(5, 88), 256, GSMEM_BYTES>>>(XA, Wt_g1,  g1_b,  P1, KP1, 56, 1280, 1280, 1280, 0);
    gemm_tf32p<<<dim3(7, 88), 256, GSMEM_BYTES>>>(XB, Wt_r11, r1_b1, Y,  KP1, 56, 1792, 1792, 1792, 1);
    gemm_tf32p<<<dim3(5, 88), 256, GSMEM_BYTES>>>(Y,  Wt_r12, r1_b2, P2, KP1, 56, 1280, 1280, 1280, 0);

    combine1_kernel<<<dim3(B_, K_), 256>>>(P1, P2, node_feature, kin, a, raw_seq, X);

    colstats_partial<<<dim3((EMB2_ + 255) / 256, NCHUNK_), 256>>>(X, psum, psq, EMB2_, M_ / NCHUNK_);
    finalize_stats<<<(EMB2_ + 255) / 256, 256>>>(psum, psq, EMB2_,
        g2_gamma, g2_beta, r2_gamma, r2_beta, s_g2, t_g2, s_r2, t_r2);
    bn_transform_kernel<<<dim3((KP2 / 2 + 255) / 256, M_), 256>>>(
        X, s_g2, t_g2, s_r2, t_r2, XA, XB, EMB2_, KP2, KP2 / 2);

    gemm_tf32p<<<dim3(5, 88), 256, GSMEM_BYTES>>>(XA, Wt_g2,  g2_b,  P1, KP2, 81, 1280, 1280, 1280, 0);
    gemm_tf32p<<<dim3(11, 88), 256, GSMEM_BYTES>>>(XB, Wt_r21, r2_b1, Y, KP2, 81, 2564, 2592, KP2, 1);
    gemm_tf32p<<<dim3(5, 88), 256, GSMEM_BYTES>>>(Y,  Wt_r22, r2_b2, P2, KP2, 81, 1280, 1280, 1280, 0);

    final_kernel<<<B_, 256>>>(P1, P2, X, a2, graph_feature);
}

// round 8
// speedup vs baseline: 1.5848x; 1.5672x over previous
#include <cuda_runtime.h>
#include <cuda_fp16.h>
#include <cstdint>

#define B_      1024
#define K_      11
#define L_KIN_  128
#define L_SUB_  64
#define L_STR_  128
#define D_SEQ_  1280
#define D_STR_  512
#define EMB_    1792
#define EMB2_   2564
#define M_      (B_ * K_)
#define NCHUNK_ 44
#define KP1     1792          // /64 = 28
#define KP2     2624          // 2564 padded to 41*64
#define NP_R21  2816

#define GBM 128
#define GBN 256
#define GSTAGES 3
#define HS 72                               // smem row stride in halves (144B: conflict-free)
#define GA_BUF (GBM * HS)                   // halves
#define GB_BUF (GBN * HS)
#define GSMEM_BYTES (GSTAGES * (GA_BUF + GB_BUF) * 2)   // 165888

__device__ float  g_X [(size_t)M_ * EMB2_];
__device__ __half g_Y [(size_t)M_ * KP2];
__device__ __half g_XA[(size_t)M_ * KP2];
__device__ __half g_XB[(size_t)M_ * KP2];
__device__ float  g_P1[(size_t)M_ * D_SEQ_];
__device__ float  g_P2[(size_t)M_ * D_SEQ_];
__device__ __half g_Wt[21905408];
__device__ float  g_kin[(size_t)B_ * D_SEQ_];
__device__ float  g_psum[NCHUNK_ * EMB2_];
__device__ float  g_psq [NCHUNK_ * EMB2_];
__device__ float  g_ss  [8 * EMB2_];

__constant__ float c_props[21 * 4] = {
    0,0,0,0,  1,0,0,0,  0,0,0,0,  0,0,0,0,  1,0,0,0,  0,0,0,0,  0,0,0,0,
    1,0,0,0,  1,0,0,0,  0,0,0,0,  0,0,1,0,  0,0,0,0,  0,0,0,1,  0,0,1,0,
    1,0,0,0,  0,0,0,1,  0,1,0,0,  0,0,0,1,  0,1,0,0,  0,1,0,0,  0,0,0,0
};

__device__ __forceinline__ float sigmoidf_(float x) { return 1.f / (1.f + expf(-x)); }

__device__ __forceinline__ void mma_f16(float* d, const unsigned* a, const unsigned* b) {
    asm volatile(
        "mma.sync.aligned.m16n8k16.row.col.f32.f16.f16.f32 "
        "{%0,%1,%2,%3}, {%4,%5,%6,%7}, {%8,%9}, {%0,%1,%2,%3};\n"
        : "+f"(d[0]), "+f"(d[1]), "+f"(d[2]), "+f"(d[3])
        : "r"(a[0]), "r"(a[1]), "r"(a[2]), "r"(a[3]), "r"(b[0]), "r"(b[1]));
}
__device__ __forceinline__ void cp16u(unsigned dst, const void* src) {
    asm volatile("cp.async.cg.shared.global [%0], [%1], 16;\n" :: "r"(dst), "l"(src));
}

// ---- fused transpose + fp16-round for all 6 weights: Wt[n][k] = (half)W[k][n] ----
__global__ __launch_bounds__(256) void transpose_all(
    const float* __restrict__ W0, const float* __restrict__ W1, const float* __restrict__ W2,
    const float* __restrict__ W3, const float* __restrict__ W4, const float* __restrict__ W5,
    __half* __restrict__ D0, __half* __restrict__ D1, __half* __restrict__ D2,
    __half* __restrict__ D3, __half* __restrict__ D4, __half* __restrict__ D5) {
    __shared__ float t[32][33];
    int bx = blockIdx.x;
    const float* W; __half* D; int K, N, KP, kb, blk;
    if      (bx < 2240)  { W=W0; D=D0; K=EMB_;  N=1280;  KP=KP1; kb=56; blk=bx; }
    else if (bx < 5376)  { W=W1; D=D1; K=EMB_;  N=1792;  KP=KP1; kb=56; blk=bx-2240; }
    else if (bx < 7616)  { W=W2; D=D2; K=EMB_;  N=1280;  KP=KP1; kb=56; blk=bx-5376; }
    else if (bx < 10896) { W=W3; D=D3; K=EMB2_; N=1280;  KP=KP2; kb=82; blk=bx-7616; }
    else if (bx < 18112) { W=W4; D=D4; K=EMB2_; N=EMB2_; KP=KP2; kb=82; blk=bx-10896; }
    else                 { W=W5; D=D5; K=EMB2_; N=1280;  KP=KP2; kb=82; blk=bx-18112; }
    int k0 = (blk % kb) * 32, n0 = (blk / kb) * 32;
    int tx = threadIdx.x & 31, ty = threadIdx.x >> 5;
    #pragma unroll
    for (int j = 0; j < 4; ++j) {
        int k = k0 + ty + j * 8, n = n0 + tx;
        t[ty + j * 8][tx] = (k < K && n < N) ? W[(size_t)k * N + n] : 0.f;
    }
    __syncthreads();
    #pragma unroll
    for (int j = 0; j < 4; ++j) {
        int n = n0 + ty + j * 8, k = k0 + tx;
        D[(size_t)n * KP + k] = __float2half(t[tx][ty + j * 8]);
    }
}

// ---- fused kin-mean + build-gfeat ----
__global__ __launch_bounds__(256) void kin_build_kernel(
    const float* __restrict__ kin_in, const float* __restrict__ sub,
    const float* __restrict__ n2, const float* __restrict__ phos,
    const int* __restrict__ position,
    float* __restrict__ kin_out, float* __restrict__ X, float* __restrict__ node_feature) {
    int b = blockIdx.x, k = blockIdx.y;
    if (k == K_) {
        const float* base = kin_in + ((size_t)b * L_KIN_ + 1) * D_SEQ_;
        for (int i = threadIdx.x; i < D_SEQ_ / 4; i += blockDim.x) {
            float4 acc = make_float4(0.f, 0.f, 0.f, 0.f);
            #pragma unroll 4
            for (int r = 0; r < L_KIN_ - 1; ++r) {
                float4 v = *(const float4*)(base + (size_t)r * D_SEQ_ + i * 4);
                acc.x += v.x; acc.y += v.y; acc.z += v.z; acc.w += v.w;
            }
            const float inv = 1.f / 127.f;
            *(float4*)(kin_out + (size_t)b * D_SEQ_ + i * 4) =
                make_float4(acc.x * inv, acc.y * inv, acc.z * inv, acc.w * inv);
        }
        return;
    }
    size_t m = (size_t)b * K_ + k;
    const float* src1 = sub + ((size_t)b * L_SUB_ + 1 + k) * D_SEQ_;
    float* dst = X + m * EMB_;
    float* nf  = node_feature + m * D_SEQ_;
    bool mid = (k == K_ / 2);
    for (int i = threadIdx.x; i < D_SEQ_ / 4; i += blockDim.x) {
        float4 v = *(const float4*)(src1 + i * 4);
        *(float4*)(nf + i * 4) = v;
        if (mid) {
            float4 p = *(const float4*)(phos + i * 4);
            v.x += p.x; v.y += p.y; v.z += p.z; v.w += p.w;
        }
        *(float4*)(dst + i * 4) = v;
    }
    int row = position[b] + k - K_ / 2;
    bool ok = (row >= 0 && row < L_STR_);
    const float* src2 = n2 + ((size_t)b * L_STR_ + (ok ? row : 0)) * D_STR_;
    for (int i = threadIdx.x; i < D_STR_ / 4; i += blockDim.x) {
        float4 v = make_float4(0.f, 0.f, 0.f, 0.f);
        if (ok) v = *(const float4*)(src2 + i * 4);
        if (mid) {
            float4 p = *(const float4*)(phos + D_SEQ_ + i * 4);
            v.x += p.x; v.y += p.y; v.z += p.z; v.w += p.w;
        }
        *(float4*)(dst + D_SEQ_ + i * 4) = v;
    }
}

__global__ __launch_bounds__(256) void colstats_partial(
    const float* __restrict__ X, float* __restrict__ psum, float* __restrict__ psq,
    int ncols, int rows_per_chunk) {
    int col = blockIdx.x * blockDim.x + threadIdx.x;
    if (col >= ncols) return;
    int r0 = blockIdx.y * rows_per_chunk;
    float s = 0.f, q = 0.f;
    const float* p = X + (size_t)r0 * ncols + col;
    #pragma unroll 4
    for (int r = 0; r < rows_per_chunk; ++r, p += ncols) {
        float v = *p;
        s += v; q += v * v;
    }
    psum[blockIdx.y * ncols + col] = s;
    psq [blockIdx.y * ncols + col] = q;
}

__global__ __launch_bounds__(256) void finalize_stats(
    const float* __restrict__ psum, const float* __restrict__ psq, int ncols,
    const float* __restrict__ gA, const float* __restrict__ bA,
    const float* __restrict__ gB, const float* __restrict__ bB,
    float* __restrict__ sA, float* __restrict__ tA,
    float* __restrict__ sB, float* __restrict__ tB) {
    int col = blockIdx.x * blockDim.x + threadIdx.x;
    if (col >= ncols) return;
    float s = 0.f, q = 0.f;
    for (int c = 0; c < NCHUNK_; ++c) {
        s += psum[c * ncols + col];
        q += psq [c * ncols + col];
    }
    const float inv_n = 1.f / (float)M_;
    float mean = s * inv_n;
    float var  = q * inv_n - mean * mean;
    float inv  = rsqrtf(var + 1e-5f);
    float sa = gA[col] * inv; sA[col] = sa; tA[col] = bA[col] - mean * sa;
    float sb = gB[col] * inv; sB[col] = sb; tB[col] = bB[col] - mean * sb;
}

// ---- BN transform to fp16: XA = (half)relu(s1*x+t1), XB likewise; zero-fills K pad ----
__global__ __launch_bounds__(256) void bn_transform_kernel(
    const float* __restrict__ X,
    const float* __restrict__ s1, const float* __restrict__ t1,
    const float* __restrict__ s2, const float* __restrict__ t2,
    __half* __restrict__ XA, __half* __restrict__ XB, int ncols, int ldo, int nj) {
    int j = blockIdx.x * blockDim.x + threadIdx.x;
    if (j >= nj) return;
    int row = blockIdx.y;
    int c = j * 2;
    const float* xr = X + (size_t)row * ncols;
    float a0 = 0.f, a1 = 0.f, b0 = 0.f, b1 = 0.f;
    if (c < ncols) {           // ncols even -> c+1 < ncols too
        float v0 = xr[c], v1 = xr[c + 1];
        a0 = fmaxf(fmaf(v0, s1[c], t1[c]), 0.f);
        a1 = fmaxf(fmaf(v1, s1[c + 1], t1[c + 1]), 0.f);
        b0 = fmaxf(fmaf(v0, s2[c], t2[c]), 0.f);
        b1 = fmaxf(fmaf(v1, s2[c + 1], t2[c + 1]), 0.f);
    }
    size_t o = (size_t)row * ldo + c;
    *(__half2*)(XA + o) = __floats2half2_rn(a0, a1);
    *(__half2*)(XB + o) = __floats2half2_rn(b0, b1);
}

// ---- fp16 GEMM m16n8k16, 128x256x64, 3-stage cp.async ----
// Cf != null: float out (+bias). Ch != null: half out = relu(v+bias), zero-fill [Nout,Nzero).
__global__ __launch_bounds__(256, 1) void gemm_f16(
    const __half* __restrict__ A, const __half* __restrict__ Wt,
    const float* __restrict__ bias, float* __restrict__ Cf, __half* __restrict__ Ch,
    int lda, int ktiles, int Nout, int Nzero, int ldc) {
    extern __shared__ __half smh[];
    __half* sA = smh;
    __half* sB = smh + GSTAGES * GA_BUF;
    const unsigned sA_u = (unsigned)__cvta_generic_to_shared(sA);
    const unsigned sB_u = (unsigned)__cvta_generic_to_shared(sB);

    const int tid  = threadIdx.x;
    const int bm   = blockIdx.y * GBM;
    const int bn   = blockIdx.x * GBN;
    const int warp = tid >> 5, lane = tid & 31;
    const int wm = (warp & 1) << 6;
    const int wn = (warp >> 1) << 6;
    const int g  = lane >> 2, tg = lane & 3;

    float acc[4][8][4];
    #pragma unroll
    for (int mt = 0; mt < 4; ++mt)
        #pragma unroll
        for (int nt = 0; nt < 8; ++nt)
            #pragma unroll
            for (int i = 0; i < 4; ++i) acc[mt][nt][i] = 0.f;

    auto load_stage = [&](int kt, int buf) {
        const int k0 = kt * 64;
        unsigned sab = sA_u + (unsigned)(buf * GA_BUF) * 2u;
        #pragma unroll
        for (int it = 0; it < 4; ++it) {
            int idx = tid + it * 256;
            int row = idx >> 3, seg = idx & 7;
            cp16u(sab + (unsigned)(row * HS + seg * 8) * 2u,
                  A + (size_t)(bm + row) * lda + k0 + seg * 8);
        }
        unsigned sbb = sB_u + (unsigned)(buf * GB_BUF) * 2u;
        #pragma unroll
        for (int it = 0; it < 8; ++it) {
            int idx = tid + it * 256;
            int row = idx >> 3, seg = idx & 7;
            cp16u(sbb + (unsigned)(row * HS + seg * 8) * 2u,
                  Wt + (size_t)(bn + row) * lda + k0 + seg * 8);
        }
        asm volatile("cp.async.commit_group;\n");
    };

    auto compute = [&](int buf) {
        const __half* pA = sA + buf * GA_BUF;
        const __half* pB = sB + buf * GB_BUF;
        #pragma unroll
        for (int kk = 0; kk < 4; ++kk) {
            const int ko = kk * 16 + tg * 2;
            unsigned af[4][4], bf[8][2];
            #pragma unroll
            for (int mt = 0; mt < 4; ++mt) {
                int r = wm + (mt << 4);
                af[mt][0] = *(const unsigned*)&pA[(r + g) * HS + ko];
                af[mt][1] = *(const unsigned*)&pA[(r + g + 8) * HS + ko];
                af[mt][2] = *(const unsigned*)&pA[(r + g) * HS + ko + 8];
                af[mt][3] = *(const unsigned*)&pA[(r + g + 8) * HS + ko + 8];
            }
            #pragma unroll
            for (int nt = 0; nt < 8; ++nt) {
                int c = wn + (nt << 3) + g;
                bf[nt][0] = *(const unsigned*)&pB[c * HS + ko];
                bf[nt][1] = *(const unsigned*)&pB[c * HS + ko + 8];
            }
            #pragma unroll
            for (int mt = 0; mt < 4; ++mt)
                #pragma unroll
                for (int nt = 0; nt < 8; ++nt)
                    mma_f16(acc[mt][nt], af[mt], bf[nt]);
        }
    };

    #pragma unroll
    for (int s = 0; s < GSTAGES - 1; ++s) load_stage(s, s);

    for (int kt = 0; kt < ktiles; ++kt) {
        asm volatile("cp.async.wait_group %0;\n" :: "n"(GSTAGES - 2));
        __syncthreads();
        int nxt = kt + GSTAGES - 1;
        if (nxt < ktiles) load_stage(nxt, nxt % GSTAGES);
        else asm volatile("cp.async.commit_group;\n");
        compute(kt % GSTAGES);
    }

    #pragma unroll
    for (int mt = 0; mt < 4; ++mt) {
        int r = bm + wm + (mt << 4);
        #pragma unroll
        for (int nt = 0; nt < 8; ++nt) {
            int c = bn + wn + (nt << 3) + (tg << 1);
            #pragma unroll
            for (int half = 0; half < 2; ++half) {
                int cc = c + half;
                if (cc >= Nzero) continue;
                float v0 = 0.f, v1 = 0.f;
                if (cc < Nout) {
                    float bb = bias[cc];
                    v0 = acc[mt][nt][half]     + bb;
                    v1 = acc[mt][nt][half + 2] + bb;
                }
                if (Ch) {
                    Ch[(size_t)(r + g) * ldc + cc]     = __float2half(fmaxf(v0, 0.f));
                    Ch[(size_t)(r + g + 8) * ldc + cc] = __float2half(fmaxf(v1, 0.f));
                } else if (cc < Nout) {
                    Cf[(size_t)(r + g) * ldc + cc]     = v0;
                    Cf[(size_t)(r + g + 8) * ldc + cc] = v1;
                }
            }
        }
    }
}

__global__ __launch_bounds__(256) void combine1_kernel(
    const float* __restrict__ F1, const float* __restrict__ F2,
    const float* __restrict__ nf, const float* __restrict__ kin,
    const float* __restrict__ a, const int* __restrict__ raw_seq,
    float* __restrict__ X2) {
    int b = blockIdx.x, k = blockIdx.y;
    size_t m = (size_t)b * K_ + k;
    float a0 = a[0], a1 = a[1];
    const float* f1 = F1 + m * D_SEQ_;
    const float* f2 = F2 + m * D_SEQ_;
    const float* g1 = nf + m * D_SEQ_;
    const float* kb = kin + (size_t)b * D_SEQ_;
    float* dst = X2 + m * EMB2_;
    for (int i = threadIdx.x; i < D_SEQ_ / 4; i += blockDim.x) {
        float4 v1 = *(const float4*)(f1 + i * 4);
        float4 v2 = *(const float4*)(f2 + i * 4);
        float4 vg = *(const float4*)(g1 + i * 4);
        float4 r;
        r.x = sigmoidf_(v1.x) * vg.x * a0 + v2.x * a1;
        r.y = sigmoidf_(v1.y) * vg.y * a0 + v2.y * a1;
        r.z = sigmoidf_(v1.z) * vg.z * a0 + v2.z * a1;
        r.w = sigmoidf_(v1.w) * vg.w * a0 + v2.w * a1;
        *(float4*)(dst + i * 4) = r;
        *(float4*)(dst + D_SEQ_ + i * 4) = *(const float4*)(kb + i * 4);
    }
    if (threadIdx.x < 4) {
        int sid = raw_seq[m];
        dst[2 * D_SEQ_ + threadIdx.x] = c_props[sid * 4 + threadIdx.x];
    }
}

__global__ __launch_bounds__(256) void final_kernel(
    const float* __restrict__ G1, const float* __restrict__ G2,
    const float* __restrict__ X2, const float* __restrict__ a2,
    float* __restrict__ out) {
    int b = blockIdx.x;
    float s0 = a2[0], s1 = a2[1];
    for (int i = threadIdx.x; i < D_SEQ_ / 4; i += blockDim.x) {
        float4 acc = make_float4(0.f, 0.f, 0.f, 0.f);
        for (int k = 0; k < K_; ++k) {
            size_t m = (size_t)b * K_ + k;
            float4 f1 = *(const float4*)(G1 + m * D_SEQ_ + i * 4);
            float4 f2 = *(const float4*)(G2 + m * D_SEQ_ + i * 4);
            float4 gn = *(const float4*)(X2 + m * EMB2_ + i * 4);
            acc.x += sigmoidf_(f1.x) * gn.x * s0 + f2.x * s1;
            acc.y += sigmoidf_(f1.y) * gn.y * s0 + f2.y * s1;
            acc.z += sigmoidf_(f1.z) * gn.z * s0 + f2.z * s1;
            acc.w += sigmoidf_(f1.w) * gn.w * s0 + f2.w * s1;
        }
        *(float4*)(out + (size_t)b * D_SEQ_ + i * 4) = acc;
    }
}

extern "C" void kernel_launch(void* const* d_in, const int* in_sizes, int n_in,
                              void* d_out, int out_size) {
    const float* kin_in   = (const float*)d_in[0];
    const float* sub      = (const float*)d_in[1];
    const float* n2       = (const float*)d_in[2];
    const float* a        = (const float*)d_in[4];
    const float* a2       = (const float*)d_in[5];
    const float* phos     = (const float*)d_in[6];
    const float* g1_gamma = (const float*)d_in[7];
    const float* g1_beta  = (const float*)d_in[8];
    const float* g1_W     = (const float*)d_in[9];
    const float* g1_b     = (const float*)d_in[10];
    const float* r1_gamma = (const float*)d_in[11];
    const float* r1_beta  = (const float*)d_in[12];
    const float* r1_W1    = (const float*)d_in[13];
    const float* r1_b1    = (const float*)d_in[14];
    const float* r1_W2    = (const float*)d_in[15];
    const float* r1_b2    = (const float*)d_in[16];
    const float* g2_gamma = (const float*)d_in[17];
    const float* g2_beta  = (const float*)d_in[18];
    const float* g2_W     = (const float*)d_in[19];
    const float* g2_b     = (const float*)d_in[20];
    const float* r2_gamma = (const float*)d_in[21];
    const float* r2_beta  = (const float*)d_in[22];
    const float* r2_W1    = (const float*)d_in[23];
    const float* r2_b1    = (const float*)d_in[24];
    const float* r2_W2    = (const float*)d_in[25];
    const float* r2_b2    = (const float*)d_in[26];
    const int*   position = (const int*)d_in[27];
    const int*   raw_seq  = (const int*)d_in[28];

    float* out = (float*)d_out;
    float* graph_feature = out;
    float* node_feature  = out + (size_t)B_ * D_SEQ_;

    float *X, *P1, *P2, *kin, *psum, *psq, *ss;
    __half *Y, *XA, *XB, *Wt;
    cudaGetSymbolAddress((void**)&X,    g_X);
    cudaGetSymbolAddress((void**)&Y,    g_Y);
    cudaGetSymbolAddress((void**)&XA,   g_XA);
    cudaGetSymbolAddress((void**)&XB,   g_XB);
    cudaGetSymbolAddress((void**)&P1,   g_P1);
    cudaGetSymbolAddress((void**)&P2,   g_P2);
    cudaGetSymbolAddress((void**)&Wt,   g_Wt);
    cudaGetSymbolAddress((void**)&kin,  g_kin);
    cudaGetSymbolAddress((void**)&psum, g_psum);
    cudaGetSymbolAddress((void**)&psq,  g_psq);
    cudaGetSymbolAddress((void**)&ss,   g_ss);

    cudaFuncSetAttribute(gemm_f16, cudaFuncAttributeMaxDynamicSharedMemorySize, GSMEM_BYTES);

    float* s_g1 = ss + 0 * EMB2_;  float* t_g1 = ss + 1 * EMB2_;
    float* s_r1 = ss + 2 * EMB2_;  float* t_r1 = ss + 3 * EMB2_;
    float* s_g2 = ss + 4 * EMB2_;  float* t_g2 = ss + 5 * EMB2_;
    float* s_r2 = ss + 6 * EMB2_;  float* t_r2 = ss + 7 * EMB2_;

    __half* Wt_g1  = Wt;
    __half* Wt_r11 = Wt_g1  + (size_t)1280 * KP1;
    __half* Wt_r12 = Wt_r11 + (size_t)1792 * KP1;
    __half* Wt_g2  = Wt_r12 + (size_t)1280 * KP1;
    __half* Wt_r21 = Wt_g2  + (size_t)1280 * KP2;
    __half* Wt_r22 = Wt_r21 + (size_t)NP_R21 * KP2;

    transpose_all<<<21392, 256>>>(g1_W, r1_W1, r1_W2, g2_W, r2_W1, r2_W2,
                                  Wt_g1, Wt_r11, Wt_r12, Wt_g2, Wt_r21, Wt_r22);
    kin_build_kernel<<<dim3(B_, K_ + 1), 256>>>(kin_in, sub, n2, phos, position,
                                                kin, X, node_feature);
    colstats_partial<<<dim3((EMB_ + 255) / 256, NCHUNK_), 256>>>(X, psum, psq, EMB_, M_ / NCHUNK_);
    finalize_stats<<<(EMB_ + 255) / 256, 256>>>(psum, psq, EMB_,
        g1_gamma, g1_beta, r1_gamma, r1_beta, s_g1, t_g1, s_r1, t_r1);
    bn_transform_kernel<<<dim3((KP1 / 2 + 255) / 256, M_), 256>>>(
        X, s_g1, t_g1, s_r1, t_r1, XA, XB, EMB_, KP1, KP1 / 2);

    // stage-1 GEMMs (ktiles = KP1/64 = 28)
    gemm_f16<<<dim3(5, 88), 256, GSMEM_BYTES>>>(XA, Wt_g1,  g1_b,  P1, nullptr, KP1, 28, 1280, 1280, 1280);
    gemm_f16<<<dim3(7, 88), 256, GSMEM_BYTES>>>(XB, Wt_r11, r1_b1, nullptr, Y,   KP1, 28, 1792, 1792, KP1);
    gemm_f16<<<dim3(5, 88), 256, GSMEM_BYTES>>>(Y,  Wt_r12, r1_b2, P2, nullptr, KP1, 28, 1280, 1280, 1280);

    combine1_kernel<<<dim3(B_, K_), 256>>>(P1, P2, node_feature, kin, a, raw_seq, X);

    colstats_partial<<<dim3((EMB2_ + 255) / 256, NCHUNK_), 256>>>(X, psum, psq, EMB2_, M_ / NCHUNK_);
    finalize_stats<<<(EMB2_ + 255) / 256, 256>>>(psum, psq, EMB2_,
        g2_gamma, g2_beta, r2_gamma, r2_beta, s_g2, t_g2, s_r2, t_r2);
    bn_transform_kernel<<<dim3((KP2 / 2 + 255) / 256, M_), 256>>>(
        X, s_g2, t_g2, s_r2, t_r2, XA, XB, EMB2_, KP2, KP2 / 2);

    // stage-2 GEMMs (ktiles = KP2/64 = 41)
    gemm_f16<<<dim3(5, 88), 256, GSMEM_BYTES>>>(XA, Wt_g2,  g2_b,  P1, nullptr, KP2, 41, 1280, 1280, 1280);
    gemm_f16<<<dim3(11, 88), 256, GSMEM_BYTES>>>(XB, Wt_r21, r2_b1, nullptr, Y,  KP2, 41, 2564, KP2, KP2);
    gemm_f16<<<dim3(5, 88), 256, GSMEM_BYTES>>>(Y,  Wt_r22, r2_b2, P2, nullptr, KP2, 41, 1280, 1280, 1280);

    final_kernel<<<B_, 256>>>(P1, P2, X, a2, graph_feature);
}

// round 9
// speedup vs baseline: 1.7822x; 1.1246x over previous
#include <cuda_runtime.h>
#include <cuda_fp16.h>
#include <cstdint>

#define B_      1024
#define K_      11
#define L_KIN_  128
#define L_SUB_  64
#define L_STR_  128
#define D_SEQ_  1280
#define D_STR_  512
#define EMB_    1792
#define EMB2_   2564
#define M_      (B_ * K_)
#define NCHUNK_ 44
#define KP1     1792          // /64 = 28
#define KP2     2624          // 2564 padded to 41*64
#define NP_R21  2816

#define GBM 128
#define GBN 128
#define GSTAGES 3
#define HS 72                               // smem row stride in halves (144B)
#define GA_BUF (GBM * HS)
#define GB_BUF (GBN * HS)
#define GSMEM_BYTES (GSTAGES * (GA_BUF + GB_BUF) * 2)   // 110592

__device__ float  g_X [(size_t)M_ * EMB2_];
__device__ __half g_Y [(size_t)M_ * KP2];
__device__ __half g_XA[(size_t)M_ * KP2];
__device__ __half g_XB[(size_t)M_ * KP2];
__device__ float  g_P1[(size_t)M_ * D_SEQ_];
__device__ float  g_P2[(size_t)M_ * D_SEQ_];
__device__ __half g_Wt[21905408];
__device__ float  g_kin[(size_t)B_ * D_SEQ_];
__device__ float  g_psum[NCHUNK_ * EMB2_];
__device__ float  g_psq [NCHUNK_ * EMB2_];
__device__ float  g_ss  [8 * EMB2_];

__constant__ float c_props[21 * 4] = {
    0,0,0,0,  1,0,0,0,  0,0,0,0,  0,0,0,0,  1,0,0,0,  0,0,0,0,  0,0,0,0,
    1,0,0,0,  1,0,0,0,  0,0,0,0,  0,0,1,0,  0,0,0,0,  0,0,0,1,  0,0,1,0,
    1,0,0,0,  0,0,0,1,  0,1,0,0,  0,0,0,1,  0,1,0,0,  0,1,0,0,  0,0,0,0
};

__device__ __forceinline__ float sigmoidf_(float x) { return 1.f / (1.f + expf(-x)); }

__device__ __forceinline__ void mma_f16(float* d, const unsigned* a, const unsigned* b) {
    asm volatile(
        "mma.sync.aligned.m16n8k16.row.col.f32.f16.f16.f32 "
        "{%0,%1,%2,%3}, {%4,%5,%6,%7}, {%8,%9}, {%0,%1,%2,%3};\n"
        : "+f"(d[0]), "+f"(d[1]), "+f"(d[2]), "+f"(d[3])
        : "r"(a[0]), "r"(a[1]), "r"(a[2]), "r"(a[3]), "r"(b[0]), "r"(b[1]));
}
__device__ __forceinline__ void cp16u(unsigned dst, const void* src) {
    asm volatile("cp.async.cg.shared.global [%0], [%1], 16;\n" :: "r"(dst), "l"(src));
}
__device__ __forceinline__ void ldm4(unsigned& r0, unsigned& r1, unsigned& r2, unsigned& r3,
                                     unsigned addr) {
    asm volatile("ldmatrix.sync.aligned.m8n8.x4.shared.b16 {%0,%1,%2,%3}, [%4];"
                 : "=r"(r0), "=r"(r1), "=r"(r2), "=r"(r3) : "r"(addr));
}

// ---- fused transpose + fp16-round for all 6 weights: Wt[n][k] = (half)W[k][n] ----
__global__ __launch_bounds__(256) void transpose_all(
    const float* __restrict__ W0, const float* __restrict__ W1, const float* __restrict__ W2,
    const float* __restrict__ W3, const float* __restrict__ W4, const float* __restrict__ W5,
    __half* __restrict__ D0, __half* __restrict__ D1, __half* __restrict__ D2,
    __half* __restrict__ D3, __half* __restrict__ D4, __half* __restrict__ D5) {
    __shared__ float t[32][33];
    int bx = blockIdx.x;
    const float* W; __half* D; int K, N, KP, kb, blk;
    if      (bx < 2240)  { W=W0; D=D0; K=EMB_;  N=1280;  KP=KP1; kb=56; blk=bx; }
    else if (bx < 5376)  { W=W1; D=D1; K=EMB_;  N=1792;  KP=KP1; kb=56; blk=bx-2240; }
    else if (bx < 7616)  { W=W2; D=D2; K=EMB_;  N=1280;  KP=KP1; kb=56; blk=bx-5376; }
    else if (bx < 10896) { W=W3; D=D3; K=EMB2_; N=1280;  KP=KP2; kb=82; blk=bx-7616; }
    else if (bx < 18112) { W=W4; D=D4; K=EMB2_; N=EMB2_; KP=KP2; kb=82; blk=bx-10896; }
    else                 { W=W5; D=D5; K=EMB2_; N=1280;  KP=KP2; kb=82; blk=bx-18112; }
    int k0 = (blk % kb) * 32, n0 = (blk / kb) * 32;
    int tx = threadIdx.x & 31, ty = threadIdx.x >> 5;
    #pragma unroll
    for (int j = 0; j < 4; ++j) {
        int k = k0 + ty + j * 8, n = n0 + tx;
        t[ty + j * 8][tx] = (k < K && n < N) ? W[(size_t)k * N + n] : 0.f;
    }
    __syncthreads();
    #pragma unroll
    for (int j = 0; j < 4; ++j) {
        int n = n0 + ty + j * 8, k = k0 + tx;
        D[(size_t)n * KP + k] = __float2half(t[tx][ty + j * 8]);
    }
}

// ---- fused kin-mean + build-gfeat ----
__global__ __launch_bounds__(256) void kin_build_kernel(
    const float* __restrict__ kin_in, const float* __restrict__ sub,
    const float* __restrict__ n2, const float* __restrict__ phos,
    const int* __restrict__ position,
    float* __restrict__ kin_out, float* __restrict__ X, float* __restrict__ node_feature) {
    int b = blockIdx.x, k = blockIdx.y;
    if (k == K_) {
        const float* base = kin_in + ((size_t)b * L_KIN_ + 1) * D_SEQ_;
        for (int i = threadIdx.x; i < D_SEQ_ / 4; i += blockDim.x) {
            float4 acc = make_float4(0.f, 0.f, 0.f, 0.f);
            #pragma unroll 4
            for (int r = 0; r < L_KIN_ - 1; ++r) {
                float4 v = *(const float4*)(base + (size_t)r * D_SEQ_ + i * 4);
                acc.x += v.x; acc.y += v.y; acc.z += v.z; acc.w += v.w;
            }
            const float inv = 1.f / 127.f;
            *(float4*)(kin_out + (size_t)b * D_SEQ_ + i * 4) =
                make_float4(acc.x * inv, acc.y * inv, acc.z * inv, acc.w * inv);
        }
        return;
    }
    size_t m = (size_t)b * K_ + k;
    const float* src1 = sub + ((size_t)b * L_SUB_ + 1 + k) * D_SEQ_;
    float* dst = X + m * EMB_;
    float* nf  = node_feature + m * D_SEQ_;
    bool mid = (k == K_ / 2);
    for (int i = threadIdx.x; i < D_SEQ_ / 4; i += blockDim.x) {
        float4 v = *(const float4*)(src1 + i * 4);
        *(float4*)(nf + i * 4) = v;
        if (mid) {
            float4 p = *(const float4*)(phos + i * 4);
            v.x += p.x; v.y += p.y; v.z += p.z; v.w += p.w;
        }
        *(float4*)(dst + i * 4) = v;
    }
    int row = position[b] + k - K_ / 2;
    bool ok = (row >= 0 && row < L_STR_);
    const float* src2 = n2 + ((size_t)b * L_STR_ + (ok ? row : 0)) * D_STR_;
    for (int i = threadIdx.x; i < D_STR_ / 4; i += blockDim.x) {
        float4 v = make_float4(0.f, 0.f, 0.f, 0.f);
        if (ok) v = *(const float4*)(src2 + i * 4);
        if (mid) {
            float4 p = *(const float4*)(phos + D_SEQ_ + i * 4);
            v.x += p.x; v.y += p.y; v.z += p.z; v.w += p.w;
        }
        *(float4*)(dst + D_SEQ_ + i * 4) = v;
    }
}

__global__ __launch_bounds__(256) void colstats_partial(
    const float* __restrict__ X, float* __restrict__ psum, float* __restrict__ psq,
    int ncols, int rows_per_chunk) {
    int col = blockIdx.x * blockDim.x + threadIdx.x;
    if (col >= ncols) return;
    int r0 = blockIdx.y * rows_per_chunk;
    float s = 0.f, q = 0.f;
    const float* p = X + (size_t)r0 * ncols + col;
    #pragma unroll 4
    for (int r = 0; r < rows_per_chunk; ++r, p += ncols) {
        float v = *p;
        s += v; q += v * v;
    }
    psum[blockIdx.y * ncols + col] = s;
    psq [blockIdx.y * ncols + col] = q;
}

__global__ __launch_bounds__(256) void finalize_stats(
    const float* __restrict__ psum, const float* __restrict__ psq, int ncols,
    const float* __restrict__ gA, const float* __restrict__ bA,
    const float* __restrict__ gB, const float* __restrict__ bB,
    float* __restrict__ sA, float* __restrict__ tA,
    float* __restrict__ sB, float* __restrict__ tB) {
    int col = blockIdx.x * blockDim.x + threadIdx.x;
    if (col >= ncols) return;
    float s = 0.f, q = 0.f;
    for (int c = 0; c < NCHUNK_; ++c) {
        s += psum[c * ncols + col];
        q += psq [c * ncols + col];
    }
    const float inv_n = 1.f / (float)M_;
    float mean = s * inv_n;
    float var  = q * inv_n - mean * mean;
    float inv  = rsqrtf(var + 1e-5f);
    float sa = gA[col] * inv; sA[col] = sa; tA[col] = bA[col] - mean * sa;
    float sb = gB[col] * inv; sB[col] = sb; tB[col] = bB[col] - mean * sb;
}

// ---- BN transform to fp16 ----
__global__ __launch_bounds__(256) void bn_transform_kernel(
    const float* __restrict__ X,
    const float* __restrict__ s1, const float* __restrict__ t1,
    const float* __restrict__ s2, const float* __restrict__ t2,
    __half* __restrict__ XA, __half* __restrict__ XB, int ncols, int ldo, int nj) {
    int j = blockIdx.x * blockDim.x + threadIdx.x;
    if (j >= nj) return;
    int row = blockIdx.y;
    int c = j * 2;
    const float* xr = X + (size_t)row * ncols;
    float a0 = 0.f, a1 = 0.f, b0 = 0.f, b1 = 0.f;
    if (c < ncols) {
        float v0 = xr[c], v1 = xr[c + 1];
        a0 = fmaxf(fmaf(v0, s1[c], t1[c]), 0.f);
        a1 = fmaxf(fmaf(v1, s1[c + 1], t1[c + 1]), 0.f);
        b0 = fmaxf(fmaf(v0, s2[c], t2[c]), 0.f);
        b1 = fmaxf(fmaf(v1, s2[c + 1], t2[c + 1]), 0.f);
    }
    size_t o = (size_t)row * ldo + c;
    *(__half2*)(XA + o) = __floats2half2_rn(a0, a1);
    *(__half2*)(XB + o) = __floats2half2_rn(b0, b1);
}

// ---- fp16 GEMM m16n8k16, 128x128x64, 3-stage cp.async, 2 CTAs/SM, ldmatrix ----
__global__ __launch_bounds__(256, 2) void gemm_f16(
    const __half* __restrict__ A, const __half* __restrict__ Wt,
    const float* __restrict__ bias, float* __restrict__ Cf, __half* __restrict__ Ch,
    int lda, int ktiles, int Nout, int Nzero, int ldc) {
    extern __shared__ __half smh[];
    const unsigned sA_u = (unsigned)__cvta_generic_to_shared(smh);
    const unsigned sB_u = sA_u + (unsigned)(GSTAGES * GA_BUF) * 2u;

    const int tid  = threadIdx.x;
    const int bm   = blockIdx.y * GBM;
    const int bn   = blockIdx.x * GBN;
    const int warp = tid >> 5, lane = tid & 31;
    const int wm = (warp & 1) << 6;      // 0,64
    const int wn = (warp >> 1) << 5;     // 0,32,64,96
    const int g  = lane >> 2, tg = lane & 3;

    // ldmatrix per-lane addressing (t = lane>>3 selects the 8x8 tile)
    const int t    = lane >> 3;
    const int a_m  = ((t & 1) << 3) + (lane & 7);
    const int a_ko = (t >> 1) << 3;
    const int b_n  = ((t >> 1) << 3) + (lane & 7);
    const int b_ko = (t & 1) << 3;

    float acc[4][4][4];
    #pragma unroll
    for (int mt = 0; mt < 4; ++mt)
        #pragma unroll
        for (int nt = 0; nt < 4; ++nt)
            #pragma unroll
            for (int i = 0; i < 4; ++i) acc[mt][nt][i] = 0.f;

    auto load_stage = [&](int kt, int buf) {
        const int k0 = kt * 64;
        unsigned sab = sA_u + (unsigned)(buf * GA_BUF) * 2u;
        #pragma unroll
        for (int it = 0; it < 4; ++it) {
            int idx = tid + it * 256;
            int row = idx >> 3, seg = idx & 7;
            cp16u(sab + (unsigned)(row * HS + seg * 8) * 2u,
                  A + (size_t)(bm + row) * lda + k0 + seg * 8);
        }
        unsigned sbb = sB_u + (unsigned)(buf * GB_BUF) * 2u;
        #pragma unroll
        for (int it = 0; it < 4; ++it) {
            int idx = tid + it * 256;
            int row = idx >> 3, seg = idx & 7;
            cp16u(sbb + (unsigned)(row * HS + seg * 8) * 2u,
                  Wt + (size_t)(bn + row) * lda + k0 + seg * 8);
        }
        asm volatile("cp.async.commit_group;\n");
    };

    auto compute = [&](int buf) {
        const unsigned pA = sA_u + (unsigned)(buf * GA_BUF) * 2u;
        const unsigned pB = sB_u + (unsigned)(buf * GB_BUF) * 2u;
        #pragma unroll
        for (int kk = 0; kk < 4; ++kk) {
            unsigned af[4][4], bf[4][2];
            #pragma unroll
            for (int mt = 0; mt < 4; ++mt) {
                unsigned addr = pA + (unsigned)(((wm + (mt << 4) + a_m) * HS
                                                + (kk << 4) + a_ko) << 1);
                ldm4(af[mt][0], af[mt][1], af[mt][2], af[mt][3], addr);
            }
            #pragma unroll
            for (int p = 0; p < 2; ++p) {
                unsigned addr = pB + (unsigned)(((wn + (p << 4) + b_n) * HS
                                                + (kk << 4) + b_ko) << 1);
                ldm4(bf[2*p][0], bf[2*p][1], bf[2*p+1][0], bf[2*p+1][1], addr);
            }
            #pragma unroll
            for (int mt = 0; mt < 4; ++mt)
                #pragma unroll
                for (int nt = 0; nt < 4; ++nt)
                    mma_f16(acc[mt][nt], af[mt], bf[nt]);
        }
    };

    #pragma unroll
    for (int s = 0; s < GSTAGES - 1; ++s) load_stage(s, s);

    for (int kt = 0; kt < ktiles; ++kt) {
        asm volatile("cp.async.wait_group %0;\n" :: "n"(GSTAGES - 2));
        __syncthreads();
        int nxt = kt + GSTAGES - 1;
        if (nxt < ktiles) load_stage(nxt, nxt % GSTAGES);
        else asm volatile("cp.async.commit_group;\n");
        compute(kt % GSTAGES);
    }

    #pragma unroll
    for (int mt = 0; mt < 4; ++mt) {
        int r = bm + wm + (mt << 4);
        #pragma unroll
        for (int nt = 0; nt < 4; ++nt) {
            int c = bn + wn + (nt << 3) + (tg << 1);
            #pragma unroll
            for (int half = 0; half < 2; ++half) {
                int cc = c + half;
                if (cc >= Nzero) continue;
                float v0 = 0.f, v1 = 0.f;
                if (cc < Nout) {
                    float bb = bias[cc];
                    v0 = acc[mt][nt][half]     + bb;
                    v1 = acc[mt][nt][half + 2] + bb;
                }
                if (Ch) {
                    Ch[(size_t)(r + g) * ldc + cc]     = __float2half(fmaxf(v0, 0.f));
                    Ch[(size_t)(r + g + 8) * ldc + cc] = __float2half(fmaxf(v1, 0.f));
                } else if (cc < Nout) {
                    Cf[(size_t)(r + g) * ldc + cc]     = v0;
                    Cf[(size_t)(r + g + 8) * ldc + cc] = v1;
                }
            }
        }
    }
}

__global__ __launch_bounds__(256) void combine1_kernel(
    const float* __restrict__ F1, const float* __restrict__ F2,
    const float* __restrict__ nf, const float* __restrict__ kin,
    const float* __restrict__ a, const int* __restrict__ raw_seq,
    float* __restrict__ X2) {
    int b = blockIdx.x, k = blockIdx.y;
    size_t m = (size_t)b * K_ + k;
    float a0 = a[0], a1 = a[1];
    const float* f1 = F1 + m * D_SEQ_;
    const float* f2 = F2 + m * D_SEQ_;
    const float* g1 = nf + m * D_SEQ_;
    const float* kb = kin + (size_t)b * D_SEQ_;
    float* dst = X2 + m * EMB2_;
    for (int i = threadIdx.x; i < D_SEQ_ / 4; i += blockDim.x) {
        float4 v1 = *(const float4*)(f1 + i * 4);
        float4 v2 = *(const float4*)(f2 + i * 4);
        float4 vg = *(const float4*)(g1 + i * 4);
        float4 r;
        r.x = sigmoidf_(v1.x) * vg.x * a0 + v2.x * a1;
        r.y = sigmoidf_(v1.y) * vg.y * a0 + v2.y * a1;
        r.z = sigmoidf_(v1.z) * vg.z * a0 + v2.z * a1;
        r.w = sigmoidf_(v1.w) * vg.w * a0 + v2.w * a1;
        *(float4*)(dst + i * 4) = r;
        *(float4*)(dst + D_SEQ_ + i * 4) = *(const float4*)(kb + i * 4);
    }
    if (threadIdx.x < 4) {
        int sid = raw_seq[m];
        dst[2 * D_SEQ_ + threadIdx.x] = c_props[sid * 4 + threadIdx.x];
    }
}

__global__ __launch_bounds__(256) void final_kernel(
    const float* __restrict__ G1, const float* __restrict__ G2,
    const float* __restrict__ X2, const float* __restrict__ a2,
    float* __restrict__ out) {
    int b = blockIdx.x;
    float s0 = a2[0], s1 = a2[1];
    for (int i = threadIdx.x; i < D_SEQ_ / 4; i += blockDim.x) {
        float4 acc = make_float4(0.f, 0.f, 0.f, 0.f);
        for (int k = 0; k < K_; ++k) {
            size_t m = (size_t)b * K_ + k;
            float4 f1 = *(const float4*)(G1 + m * D_SEQ_ + i * 4);
            float4 f2 = *(const float4*)(G2 + m * D_SEQ_ + i * 4);
            float4 gn = *(const float4*)(X2 + m * EMB2_ + i * 4);
            acc.x += sigmoidf_(f1.x) * gn.x * s0 + f2.x * s1;
            acc.y += sigmoidf_(f1.y) * gn.y * s0 + f2.y * s1;
            acc.z += sigmoidf_(f1.z) * gn.z * s0 + f2.z * s1;
            acc.w += sigmoidf_(f1.w) * gn.w * s0 + f2.w * s1;
        }
        *(float4*)(out + (size_t)b * D_SEQ_ + i * 4) = acc;
    }
}

extern "C" void kernel_launch(void* const* d_in, const int* in_sizes, int n_in,
                              void* d_out, int out_size) {
    const float* kin_in   = (const float*)d_in[0];
    const float* sub      = (const float*)d_in[1];
    const float* n2       = (const float*)d_in[2];
    const float* a        = (const float*)d_in[4];
    const float* a2       = (const float*)d_in[5];
    const float* phos     = (const float*)d_in[6];
    const float* g1_gamma = (const float*)d_in[7];
    const float* g1_beta  = (const float*)d_in[8];
    const float* g1_W     = (const float*)d_in[9];
    const float* g1_b     = (const float*)d_in[10];
    const float* r1_gamma = (const float*)d_in[11];
    const float* r1_beta  = (const float*)d_in[12];
    const float* r1_W1    = (const float*)d_in[13];
    const float* r1_b1    = (const float*)d_in[14];
    const float* r1_W2    = (const float*)d_in[15];
    const float* r1_b2    = (const float*)d_in[16];
    const float* g2_gamma = (const float*)d_in[17];
    const float* g2_beta  = (const float*)d_in[18];
    const float* g2_W     = (const float*)d_in[19];
    const float* g2_b     = (const float*)d_in[20];
    const float* r2_gamma = (const float*)d_in[21];
    const float* r2_beta  = (const float*)d_in[22];
    const float* r2_W1    = (const float*)d_in[23];
    const float* r2_b1    = (const float*)d_in[24];
    const float* r2_W2    = (const float*)d_in[25];
    const float* r2_b2    = (const float*)d_in[26];
    const int*   position = (const int*)d_in[27];
    const int*   raw_seq  = (const int*)d_in[28];

    float* out = (float*)d_out;
    float* graph_feature = out;
    float* node_feature  = out + (size_t)B_ * D_SEQ_;

    float *X, *P1, *P2, *kin, *psum, *psq, *ss;
    __half *Y, *XA, *XB, *Wt;
    cudaGetSymbolAddress((void**)&X,    g_X);
    cudaGetSymbolAddress((void**)&Y,    g_Y);
    cudaGetSymbolAddress((void**)&XA,   g_XA);
    cudaGetSymbolAddress((void**)&XB,   g_XB);
    cudaGetSymbolAddress((void**)&P1,   g_P1);
    cudaGetSymbolAddress((void**)&P2,   g_P2);
    cudaGetSymbolAddress((void**)&Wt,   g_Wt);
    cudaGetSymbolAddress((void**)&kin,  g_kin);
    cudaGetSymbolAddress((void**)&psum, g_psum);
    cudaGetSymbolAddress((void**)&psq,  g_psq);
    cudaGetSymbolAddress((void**)&ss,   g_ss);

    cudaFuncSetAttribute(gemm_f16, cudaFuncAttributeMaxDynamicSharedMemorySize, GSMEM_BYTES);

    float* s_g1 = ss + 0 * EMB2_;  float* t_g1 = ss + 1 * EMB2_;
    float* s_r1 = ss + 2 * EMB2_;  float* t_r1 = ss + 3 * EMB2_;
    float* s_g2 = ss + 4 * EMB2_;  float* t_g2 = ss + 5 * EMB2_;
    float* s_r2 = ss + 6 * EMB2_;  float* t_r2 = ss + 7 * EMB2_;

    __half* Wt_g1  = Wt;
    __half* Wt_r11 = Wt_g1  + (size_t)1280 * KP1;
    __half* Wt_r12 = Wt_r11 + (size_t)1792 * KP1;
    __half* Wt_g2  = Wt_r12 + (size_t)1280 * KP1;
    __half* Wt_r21 = Wt_g2  + (size_t)1280 * KP2;
    __half* Wt_r22 = Wt_r21 + (size_t)NP_R21 * KP2;

    transpose_all<<<21392, 256>>>(g1_W, r1_W1, r1_W2, g2_W, r2_W1, r2_W2,
                                  Wt_g1, Wt_r11, Wt_r12, Wt_g2, Wt_r21, Wt_r22);
    kin_build_kernel<<<dim3(B_, K_ + 1), 256>>>(kin_in, sub, n2, phos, position,
                                                kin, X, node_feature);
    colstats_partial<<<dim3((EMB_ + 255) / 256, NCHUNK_), 256>>>(X, psum, psq, EMB_, M_ / NCHUNK_);
    finalize_stats<<<(EMB_ + 255) / 256, 256>>>(psum, psq, EMB_,
        g1_gamma, g1_beta, r1_gamma, r1_beta, s_g1, t_g1, s_r1, t_r1);
    bn_transform_kernel<<<dim3((KP1 / 2 + 255) / 256, M_), 256>>>(
        X, s_g1, t_g1, s_r1, t_r1, XA, XB, EMB_, KP1, KP1 / 2);

    // stage-1 GEMMs (ktiles = 28)
    gemm_f16<<<dim3(10, 88), 256, GSMEM_BYTES>>>(XA, Wt_g1,  g1_b,  P1, nullptr, KP1, 28, 1280, 1280, 1280);
    gemm_f16<<<dim3(14, 88), 256, GSMEM_BYTES>>>(XB, Wt_r11, r1_b1, nullptr, Y,   KP1, 28, 1792, 1792, KP1);
    gemm_f16<<<dim3(10, 88), 256, GSMEM_BYTES>>>(Y,  Wt_r12, r1_b2, P2, nullptr, KP1, 28, 1280, 1280, 1280);

    combine1_kernel<<<dim3(B_, K_), 256>>>(P1, P2, node_feature, kin, a, raw_seq, X);

    colstats_partial<<<dim3((EMB2_ + 255) / 256, NCHUNK_), 256>>>(X, psum, psq, EMB2_, M_ / NCHUNK_);
    finalize_stats<<<(EMB2_ + 255) / 256, 256>>>(psum, psq, EMB2_,
        g2_gamma, g2_beta, r2_gamma, r2_beta, s_g2, t_g2, s_r2, t_r2);
    bn_transform_kernel<<<dim3((KP2 / 2 + 255) / 256, M_), 256>>>(
        X, s_g2, t_g2, s_r2, t_r2, XA, XB, EMB2_, KP2, KP2 / 2);

    // stage-2 GEMMs (ktiles = 41)
    gemm_f16<<<dim3(10, 88), 256, GSMEM_BYTES>>>(XA, Wt_g2,  g2_b,  P1, nullptr, KP2, 41, 1280, 1280, 1280);
    gemm_f16<<<dim3(21, 88), 256, GSMEM_BYTES>>>(XB, Wt_r21, r2_b1, nullptr, Y,  KP2, 41, 2564, KP2, KP2);
    gemm_f16<<<dim3(10, 88), 256, GSMEM_BYTES>>>(Y,  Wt_r22, r2_b2, P2, nullptr, KP2, 41, 1280, 1280, 1280);

    final_kernel<<<B_, 256>>>(P1, P2, X, a2, graph_feature);
}

// round 10
// speedup vs baseline: 1.9638x; 1.1019x over previous
#include <cuda_runtime.h>
#include <cuda_fp16.h>
#include <cstdint>

#define B_      1024
#define K_      11
#define L_KIN_  128
#define L_SUB_  64
#define L_STR_  128
#define D_SEQ_  1280
#define D_STR_  512
#define EMB_    1792
#define EMB2_   2564
#define M_      (B_ * K_)
#define NCHUNK_ 44
#define KP1     1792          // stage-1 K (28 ktiles)
#define KP2     2624          // r22 K / Wt k-stride (41 ktiles)
#define NP_R21  2816

#define GBM 128
#define GBN 128
#define GSTAGES 3
#define HS 72
#define GA_BUF (GBM * HS)
#define GB_BUF (GBN * HS)
#define GSMEM_BYTES (GSTAGES * (GA_BUF + GB_BUF) * 2)   // 110592

__device__ float  g_X [(size_t)M_ * EMB_];    // gfeat (ld EMB_), later X2 (ld 1280)
__device__ __half g_Y [(size_t)M_ * KP2];
__device__ __half g_XA[(size_t)M_ * KP1];
__device__ __half g_XB[(size_t)M_ * KP1];
__device__ __half g_KA[(size_t)B_ * D_SEQ_];
__device__ __half g_KB[(size_t)B_ * D_SEQ_];
__device__ float  g_P1[(size_t)M_ * D_SEQ_];
__device__ float  g_P2[(size_t)M_ * D_SEQ_];
__device__ __half g_Wt[21905408];
__device__ float  g_kin[(size_t)B_ * D_SEQ_];
__device__ float  g_Qg[(size_t)B_ * D_SEQ_];
__device__ float  g_Qr[(size_t)B_ * EMB2_];
__device__ float  g_Tg[21 * D_SEQ_];
__device__ float  g_Tr[21 * EMB2_];
__device__ int    g_cnt[21];
__device__ float  g_psum [NCHUNK_ * EMB_];
__device__ float  g_psq  [NCHUNK_ * EMB_];
__device__ float  g_psumK[4 * D_SEQ_];
__device__ float  g_psqK [4 * D_SEQ_];
__device__ float  g_ss  [8 * EMB2_];

__constant__ float c_props[21 * 4] = {
    0,0,0,0,  1,0,0,0,  0,0,0,0,  0,0,0,0,  1,0,0,0,  0,0,0,0,  0,0,0,0,
    1,0,0,0,  1,0,0,0,  0,0,0,0,  0,0,1,0,  0,0,0,0,  0,0,0,1,  0,0,1,0,
    1,0,0,0,  0,0,0,1,  0,1,0,0,  0,0,0,1,  0,1,0,0,  0,1,0,0,  0,0,0,0
};

__device__ __forceinline__ float sigmoidf_(float x) { return 1.f / (1.f + expf(-x)); }

__device__ __forceinline__ void mma_f16(float* d, const unsigned* a, const unsigned* b) {
    asm volatile(
        "mma.sync.aligned.m16n8k16.row.col.f32.f16.f16.f32 "
        "{%0,%1,%2,%3}, {%4,%5,%6,%7}, {%8,%9}, {%0,%1,%2,%3};\n"
        : "+f"(d[0]), "+f"(d[1]), "+f"(d[2]), "+f"(d[3])
        : "r"(a[0]), "r"(a[1]), "r"(a[2]), "r"(a[3]), "r"(b[0]), "r"(b[1]));
}
__device__ __forceinline__ void cp16u(unsigned dst, const void* src) {
    asm volatile("cp.async.cg.shared.global [%0], [%1], 16;\n" :: "r"(dst), "l"(src));
}
__device__ __forceinline__ void ldm4(unsigned& r0, unsigned& r1, unsigned& r2, unsigned& r3,
                                     unsigned addr) {
    asm volatile("ldmatrix.sync.aligned.m8n8.x4.shared.b16 {%0,%1,%2,%3}, [%4];"
                 : "=r"(r0), "=r"(r1), "=r"(r2), "=r"(r3) : "r"(addr));
}

// ---- transpose + fp16 round: Wt[n][k] = (half)W[k][n] ----
__global__ __launch_bounds__(256) void transpose_all(
    const float* __restrict__ W0, const float* __restrict__ W1, const float* __restrict__ W2,
    const float* __restrict__ W3, const float* __restrict__ W4, const float* __restrict__ W5,
    __half* __restrict__ D0, __half* __restrict__ D1, __half* __restrict__ D2,
    __half* __restrict__ D3, __half* __restrict__ D4, __half* __restrict__ D5) {
    __shared__ float t[32][33];
    int bx = blockIdx.x;
    const float* W; __half* D; int K, N, KP, kb, blk;
    if      (bx < 2240)  { W=W0; D=D0; K=EMB_;  N=1280;  KP=KP1; kb=56; blk=bx; }
    else if (bx < 5376)  { W=W1; D=D1; K=EMB_;  N=1792;  KP=KP1; kb=56; blk=bx-2240; }
    else if (bx < 7616)  { W=W2; D=D2; K=EMB_;  N=1280;  KP=KP1; kb=56; blk=bx-5376; }
    else if (bx < 10896) { W=W3; D=D3; K=EMB2_; N=1280;  KP=KP2; kb=82; blk=bx-7616; }
    else if (bx < 18112) { W=W4; D=D4; K=EMB2_; N=EMB2_; KP=KP2; kb=82; blk=bx-10896; }
    else                 { W=W5; D=D5; K=EMB2_; N=1280;  KP=KP2; kb=82; blk=bx-18112; }
    int k0 = (blk % kb) * 32, n0 = (blk / kb) * 32;
    int tx = threadIdx.x & 31, ty = threadIdx.x >> 5;
    #pragma unroll
    for (int j = 0; j < 4; ++j) {
        int k = k0 + ty + j * 8, n = n0 + tx;
        t[ty + j * 8][tx] = (k < K && n < N) ? W[(size_t)k * N + n] : 0.f;
    }
    __syncthreads();
    #pragma unroll
    for (int j = 0; j < 4; ++j) {
        int n = n0 + ty + j * 8, k = k0 + tx;
        D[(size_t)n * KP + k] = __float2half(t[tx][ty + j * 8]);
    }
}

// ---- fused kin-mean + build-gfeat ----
__global__ __launch_bounds__(256) void kin_build_kernel(
    const float* __restrict__ kin_in, const float* __restrict__ sub,
    const float* __restrict__ n2, const float* __restrict__ phos,
    const int* __restrict__ position,
    float* __restrict__ kin_out, float* __restrict__ X, float* __restrict__ node_feature) {
    int b = blockIdx.x, k = blockIdx.y;
    if (k == K_) {
        const float* base = kin_in + ((size_t)b * L_KIN_ + 1) * D_SEQ_;
        for (int i = threadIdx.x; i < D_SEQ_ / 4; i += blockDim.x) {
            float4 acc = make_float4(0.f, 0.f, 0.f, 0.f);
            #pragma unroll 4
            for (int r = 0; r < L_KIN_ - 1; ++r) {
                float4 v = *(const float4*)(base + (size_t)r * D_SEQ_ + i * 4);
                acc.x += v.x; acc.y += v.y; acc.z += v.z; acc.w += v.w;
            }
            const float inv = 1.f / 127.f;
            *(float4*)(kin_out + (size_t)b * D_SEQ_ + i * 4) =
                make_float4(acc.x * inv, acc.y * inv, acc.z * inv, acc.w * inv);
        }
        return;
    }
    size_t m = (size_t)b * K_ + k;
    const float* src1 = sub + ((size_t)b * L_SUB_ + 1 + k) * D_SEQ_;
    float* dst = X + m * EMB_;
    float* nf  = node_feature + m * D_SEQ_;
    bool mid = (k == K_ / 2);
    for (int i = threadIdx.x; i < D_SEQ_ / 4; i += blockDim.x) {
        float4 v = *(const float4*)(src1 + i * 4);
        *(float4*)(nf + i * 4) = v;
        if (mid) {
            float4 p = *(const float4*)(phos + i * 4);
            v.x += p.x; v.y += p.y; v.z += p.z; v.w += p.w;
        }
        *(float4*)(dst + i * 4) = v;
    }
    int row = position[b] + k - K_ / 2;
    bool ok = (row >= 0 && row < L_STR_);
    const float* src2 = n2 + ((size_t)b * L_STR_ + (ok ? row : 0)) * D_STR_;
    for (int i = threadIdx.x; i < D_STR_ / 4; i += blockDim.x) {
        float4 v = make_float4(0.f, 0.f, 0.f, 0.f);
        if (ok) v = *(const float4*)(src2 + i * 4);
        if (mid) {
            float4 p = *(const float4*)(phos + D_SEQ_ + i * 4);
            v.x += p.x; v.y += p.y; v.z += p.z; v.w += p.w;
        }
        *(float4*)(dst + D_SEQ_ + i * 4) = v;
    }
}

__global__ __launch_bounds__(256) void colstats_partial(
    const float* __restrict__ X, float* __restrict__ psum, float* __restrict__ psq,
    int ncols, int rows_per_chunk) {
    int col = blockIdx.x * blockDim.x + threadIdx.x;
    if (col >= ncols) return;
    int r0 = blockIdx.y * rows_per_chunk;
    float s = 0.f, q = 0.f;
    const float* p = X + (size_t)r0 * ncols + col;
    #pragma unroll 4
    for (int r = 0; r < rows_per_chunk; ++r, p += ncols) {
        float v = *p;
        s += v; q += v * v;
    }
    psum[blockIdx.y * ncols + col] = s;
    psq [blockIdx.y * ncols + col] = q;
}

// stage-1 finalize (EMB_ cols from NCHUNK_ chunks)
__global__ __launch_bounds__(256) void finalize_stats(
    const float* __restrict__ psum, const float* __restrict__ psq, int ncols,
    const float* __restrict__ gA, const float* __restrict__ bA,
    const float* __restrict__ gB, const float* __restrict__ bB,
    float* __restrict__ sA, float* __restrict__ tA,
    float* __restrict__ sB, float* __restrict__ tB) {
    int col = blockIdx.x * blockDim.x + threadIdx.x;
    if (col >= ncols) return;
    float s = 0.f, q = 0.f;
    for (int c = 0; c < NCHUNK_; ++c) {
        s += psum[c * ncols + col];
        q += psq [c * ncols + col];
    }
    const float inv_n = 1.f / (float)M_;
    float mean = s * inv_n;
    float var  = q * inv_n - mean * mean;
    float inv  = rsqrtf(var + 1e-5f);
    float sa = gA[col] * inv; sA[col] = sa; tA[col] = bA[col] - mean * sa;
    float sb = gB[col] * inv; sB[col] = sb; tB[col] = bB[col] - mean * sb;
}

// stage-2 finalize: cols 0-1279 from X2 chunks, 1280-2559 from kin chunks, 2560+ from histogram
__global__ __launch_bounds__(256) void finalize_stats2(
    const float* __restrict__ psum, const float* __restrict__ psq,
    const float* __restrict__ psumK, const float* __restrict__ psqK,
    const int* __restrict__ cnt,
    const float* __restrict__ gA, const float* __restrict__ bA,
    const float* __restrict__ gB, const float* __restrict__ bB,
    float* __restrict__ sA, float* __restrict__ tA,
    float* __restrict__ sB, float* __restrict__ tB) {
    int col = blockIdx.x * blockDim.x + threadIdx.x;
    if (col >= EMB2_) return;
    float mean, var;
    if (col < D_SEQ_) {
        float s = 0.f, q = 0.f;
        for (int c = 0; c < NCHUNK_; ++c) { s += psum[c * D_SEQ_ + col]; q += psq[c * D_SEQ_ + col]; }
        mean = s / (float)M_; var = q / (float)M_ - mean * mean;
    } else if (col < 2 * D_SEQ_) {
        int j = col - D_SEQ_;
        float s = 0.f, q = 0.f;
        for (int c = 0; c < 4; ++c) { s += psumK[c * D_SEQ_ + j]; q += psqK[c * D_SEQ_ + j]; }
        mean = s / (float)B_; var = q / (float)B_ - mean * mean;
    } else {
        int j = col - 2 * D_SEQ_;
        float s = 0.f;
        for (int sd = 0; sd < 21; ++sd) s += (float)cnt[sd] * c_props[sd * 4 + j];
        mean = s / (float)M_; var = mean - mean * mean;
    }
    float inv = rsqrtf(var + 1e-5f);
    float sa = gA[col] * inv; sA[col] = sa; tA[col] = bA[col] - mean * sa;
    float sb = gB[col] * inv; sB[col] = sb; tB[col] = bB[col] - mean * sb;
}

__global__ void hist_kernel(const int* __restrict__ seq, int* __restrict__ cnt) {
    __shared__ int h[21];
    if (threadIdx.x < 21) h[threadIdx.x] = 0;
    __syncthreads();
    for (int i = threadIdx.x; i < M_; i += blockDim.x) atomicAdd(&h[seq[i]], 1);
    __syncthreads();
    if (threadIdx.x < 21) cnt[threadIdx.x] = h[threadIdx.x];
}

// T[sid][n] = sum_j relu(s[2560+j]*props[sid][j]+t[2560+j]) * W[(2560+j)*N + n]  (exact fp32)
__global__ __launch_bounds__(256) void props_table(
    const float* __restrict__ W, const float* __restrict__ s, const float* __restrict__ t,
    float* __restrict__ T, int N) {
    int idx = blockIdx.x * blockDim.x + threadIdx.x;
    if (idx >= 21 * N) return;
    int sid = idx / N, n = idx % N;
    float acc = 0.f;
    #pragma unroll
    for (int j = 0; j < 4; ++j) {
        float pv = fmaxf(fmaf(c_props[sid * 4 + j], s[j], t[j]), 0.f);
        acc += pv * W[(size_t)(2 * D_SEQ_ + j) * N + n];
    }
    T[idx] = acc;
}

// ---- BN transform to fp16 ----
__global__ __launch_bounds__(256) void bn_transform_kernel(
    const float* __restrict__ X,
    const float* __restrict__ s1, const float* __restrict__ t1,
    const float* __restrict__ s2, const float* __restrict__ t2,
    __half* __restrict__ XA, __half* __restrict__ XB, int ncols, int ldo, int nj) {
    int j = blockIdx.x * blockDim.x + threadIdx.x;
    if (j >= nj) return;
    int row = blockIdx.y;
    int c = j * 2;
    const float* xr = X + (size_t)row * ncols;
    float a0 = 0.f, a1 = 0.f, b0 = 0.f, b1 = 0.f;
    if (c < ncols) {
        float v0 = xr[c], v1 = xr[c + 1];
        a0 = fmaxf(fmaf(v0, s1[c], t1[c]), 0.f);
        a1 = fmaxf(fmaf(v1, s1[c + 1], t1[c + 1]), 0.f);
        b0 = fmaxf(fmaf(v0, s2[c], t2[c]), 0.f);
        b1 = fmaxf(fmaf(v1, s2[c + 1], t2[c + 1]), 0.f);
    }
    size_t o = (size_t)row * ldo + c;
    *(__half2*)(XA + o) = __floats2half2_rn(a0, a1);
    *(__half2*)(XB + o) = __floats2half2_rn(b0, b1);
}

// ---- fp16 GEMM m16n8k16, 128x128x64, 3-stage, 2 CTAs/SM, ldmatrix ----
// epilogue: v = acc (+bias) (+Q[m/11][n]) (+T[seq[m]][n]); Ch: relu->half; Cf: float
__global__ __launch_bounds__(256, 2) void gemm_f16(
    const __half* __restrict__ A, const __half* __restrict__ Wt,
    const float* __restrict__ bias, float* __restrict__ Cf, __half* __restrict__ Ch,
    int lda, int ldw, int ktiles, int Nout, int Nzero, int ldc,
    const float* __restrict__ Q, int ldq,
    const float* __restrict__ T, int ldt, const int* __restrict__ seq) {
    extern __shared__ __half smh[];
    const unsigned sA_u = (unsigned)__cvta_generic_to_shared(smh);
    const unsigned sB_u = sA_u + (unsigned)(GSTAGES * GA_BUF) * 2u;

    const int tid  = threadIdx.x;
    const int bm   = blockIdx.y * GBM;
    const int bn   = blockIdx.x * GBN;
    const int warp = tid >> 5, lane = tid & 31;
    const int wm = (warp & 1) << 6;
    const int wn = (warp >> 1) << 5;
    const int g  = lane >> 2, tg = lane & 3;

    const int t    = lane >> 3;
    const int a_m  = ((t & 1) << 3) + (lane & 7);
    const int a_ko = (t >> 1) << 3;
    const int b_n  = ((t >> 1) << 3) + (lane & 7);
    const int b_ko = (t & 1) << 3;

    float acc[4][4][4];
    #pragma unroll
    for (int mt = 0; mt < 4; ++mt)
        #pragma unroll
        for (int nt = 0; nt < 4; ++nt)
            #pragma unroll
            for (int i = 0; i < 4; ++i) acc[mt][nt][i] = 0.f;

    auto load_stage = [&](int kt, int buf) {
        const int k0 = kt * 64;
        unsigned sab = sA_u + (unsigned)(buf * GA_BUF) * 2u;
        #pragma unroll
        for (int it = 0; it < 4; ++it) {
            int idx = tid + it * 256;
            int row = idx >> 3, seg = idx & 7;
            cp16u(sab + (unsigned)(row * HS + seg * 8) * 2u,
                  A + (size_t)(bm + row) * lda + k0 + seg * 8);
        }
        unsigned sbb = sB_u + (unsigned)(buf * GB_BUF) * 2u;
        #pragma unroll
        for (int it = 0; it < 4; ++it) {
            int idx = tid + it * 256;
            int row = idx >> 3, seg = idx & 7;
            cp16u(sbb + (unsigned)(row * HS + seg * 8) * 2u,
                  Wt + (size_t)(bn + row) * ldw + k0 + seg * 8);
        }
        asm volatile("cp.async.commit_group;\n");
    };

    auto compute = [&](int buf) {
        const unsigned pA = sA_u + (unsigned)(buf * GA_BUF) * 2u;
        const unsigned pB = sB_u + (unsigned)(buf * GB_BUF) * 2u;
        #pragma unroll
        for (int kk = 0; kk < 4; ++kk) {
            unsigned af[4][4], bf[4][2];
            #pragma unroll
            for (int mt = 0; mt < 4; ++mt) {
                unsigned addr = pA + (unsigned)(((wm + (mt << 4) + a_m) * HS
                                                + (kk << 4) + a_ko) << 1);
                ldm4(af[mt][0], af[mt][1], af[mt][2], af[mt][3], addr);
            }
            #pragma unroll
            for (int p = 0; p < 2; ++p) {
                unsigned addr = pB + (unsigned)(((wn + (p << 4) + b_n) * HS
                                                + (kk << 4) + b_ko) << 1);
                ldm4(bf[2*p][0], bf[2*p][1], bf[2*p+1][0], bf[2*p+1][1], addr);
            }
            #pragma unroll
            for (int mt = 0; mt < 4; ++mt)
                #pragma unroll
                for (int nt = 0; nt < 4; ++nt)
                    mma_f16(acc[mt][nt], af[mt], bf[nt]);
        }
    };

    #pragma unroll
    for (int s = 0; s < GSTAGES - 1; ++s) load_stage(s, s);

    for (int kt = 0; kt < ktiles; ++kt) {
        asm volatile("cp.async.wait_group %0;\n" :: "n"(GSTAGES - 2));
        __syncthreads();
        int nxt = kt + GSTAGES - 1;
        if (nxt < ktiles) load_stage(nxt, nxt % GSTAGES);
        else asm volatile("cp.async.commit_group;\n");
        compute(kt % GSTAGES);
    }

    #pragma unroll
    for (int mt = 0; mt < 4; ++mt) {
        int r = bm + wm + (mt << 4);
        int m0 = r + g, m1 = r + g + 8;
        const float* q0 = Q ? Q + (size_t)(m0 / 11) * ldq : nullptr;
        const float* q1 = Q ? Q + (size_t)(m1 / 11) * ldq : nullptr;
        const float* t0 = T ? T + (size_t)seq[m0] * ldt : nullptr;
        const float* t1p = T ? T + (size_t)seq[m1] * ldt : nullptr;
        #pragma unroll
        for (int nt = 0; nt < 4; ++nt) {
            int c = bn + wn + (nt << 3) + (tg << 1);
            #pragma unroll
            for (int half = 0; half < 2; ++half) {
                int cc = c + half;
                if (cc >= Nzero) continue;
                float v0 = 0.f, v1 = 0.f;
                if (cc < Nout) {
                    float bb = bias ? bias[cc] : 0.f;
                    v0 = acc[mt][nt][half]     + bb;
                    v1 = acc[mt][nt][half + 2] + bb;
                    if (q0) { v0 += q0[cc]; v1 += q1[cc]; }
                    if (t0) { v0 += t0[cc]; v1 += t1p[cc]; }
                }
                if (Ch) {
                    Ch[(size_t)m0 * ldc + cc] = __float2half(fmaxf(v0, 0.f));
                    Ch[(size_t)m1 * ldc + cc] = __float2half(fmaxf(v1, 0.f));
                } else if (cc < Nout) {
                    Cf[(size_t)m0 * ldc + cc] = v0;
                    Cf[(size_t)m1 * ldc + cc] = v1;
                }
            }
        }
    }
}

// ---- combine stage 1 -> X2 (gfeat only, ld 1280) ----
__global__ __launch_bounds__(256) void combine1_kernel(
    const float* __restrict__ F1, const float* __restrict__ F2,
    const float* __restrict__ nf, const float* __restrict__ a,
    float* __restrict__ X2) {
    int b = blockIdx.x, k = blockIdx.y;
    size_t m = (size_t)b * K_ + k;
    float a0 = a[0], a1 = a[1];
    const float* f1 = F1 + m * D_SEQ_;
    const float* f2 = F2 + m * D_SEQ_;
    const float* g1 = nf + m * D_SEQ_;
    float* dst = X2 + m * D_SEQ_;
    for (int i = threadIdx.x; i < D_SEQ_ / 4; i += blockDim.x) {
        float4 v1 = *(const float4*)(f1 + i * 4);
        float4 v2 = *(const float4*)(f2 + i * 4);
        float4 vg = *(const float4*)(g1 + i * 4);
        float4 r;
        r.x = sigmoidf_(v1.x) * vg.x * a0 + v2.x * a1;
        r.y = sigmoidf_(v1.y) * vg.y * a0 + v2.y * a1;
        r.z = sigmoidf_(v1.z) * vg.z * a0 + v2.z * a1;
        r.w = sigmoidf_(v1.w) * vg.w * a0 + v2.w * a1;
        *(float4*)(dst + i * 4) = r;
    }
}

__global__ __launch_bounds__(256) void final_kernel(
    const float* __restrict__ G1, const float* __restrict__ G2,
    const float* __restrict__ X2, const float* __restrict__ a2,
    float* __restrict__ out) {
    int b = blockIdx.x;
    float s0 = a2[0], s1 = a2[1];
    for (int i = threadIdx.x; i < D_SEQ_ / 4; i += blockDim.x) {
        float4 acc = make_float4(0.f, 0.f, 0.f, 0.f);
        for (int k = 0; k < K_; ++k) {
            size_t m = (size_t)b * K_ + k;
            float4 f1 = *(const float4*)(G1 + m * D_SEQ_ + i * 4);
            float4 f2 = *(const float4*)(G2 + m * D_SEQ_ + i * 4);
            float4 gn = *(const float4*)(X2 + m * D_SEQ_ + i * 4);
            acc.x += sigmoidf_(f1.x) * gn.x * s0 + f2.x * s1;
            acc.y += sigmoidf_(f1.y) * gn.y * s0 + f2.y * s1;
            acc.z += sigmoidf_(f1.z) * gn.z * s0 + f2.z * s1;
            acc.w += sigmoidf_(f1.w) * gn.w * s0 + f2.w * s1;
        }
        *(float4*)(out + (size_t)b * D_SEQ_ + i * 4) = acc;
    }
}

extern "C" void kernel_launch(void* const* d_in, const int* in_sizes, int n_in,
                              void* d_out, int out_size) {
    const float* kin_in   = (const float*)d_in[0];
    const float* sub      = (const float*)d_in[1];
    const float* n2       = (const float*)d_in[2];
    const float* a        = (const float*)d_in[4];
    const float* a2       = (const float*)d_in[5];
    const float* phos     = (const float*)d_in[6];
    const float* g1_gamma = (const float*)d_in[7];
    const float* g1_beta  = (const float*)d_in[8];
    const float* g1_W     = (const float*)d_in[9];
    const float* g1_b     = (const float*)d_in[10];
    const float* r1_gamma = (const float*)d_in[11];
    const float* r1_beta  = (const float*)d_in[12];
    const float* r1_W1    = (const float*)d_in[13];
    const float* r1_b1    = (const float*)d_in[14];
    const float* r1_W2    = (const float*)d_in[15];
    const float* r1_b2    = (const float*)d_in[16];
    const float* g2_gamma = (const float*)d_in[17];
    const float* g2_beta  = (const float*)d_in[18];
    const float* g2_W     = (const float*)d_in[19];
    const float* g2_b     = (const float*)d_in[20];
    const float* r2_gamma = (const float*)d_in[21];
    const float* r2_beta  = (const float*)d_in[22];
    const float* r2_W1    = (const float*)d_in[23];
    const float* r2_b1    = (const float*)d_in[24];
    const float* r2_W2    = (const float*)d_in[25];
    const float* r2_b2    = (const float*)d_in[26];
    const int*   position = (const int*)d_in[27];
    const int*   raw_seq  = (const int*)d_in[28];

    float* out = (float*)d_out;
    float* graph_feature = out;
    float* node_feature  = out + (size_t)B_ * D_SEQ_;

    float *X, *P1, *P2, *kin, *Qg, *Qr, *Tg, *Tr, *psum, *psq, *psumK, *psqK, *ss;
    int* cnt;
    __half *Y, *XA, *XB, *KA, *KB, *Wt;
    cudaGetSymbolAddress((void**)&X,     g_X);
    cudaGetSymbolAddress((void**)&Y,     g_Y);
    cudaGetSymbolAddress((void**)&XA,    g_XA);
    cudaGetSymbolAddress((void**)&XB,    g_XB);
    cudaGetSymbolAddress((void**)&KA,    g_KA);
    cudaGetSymbolAddress((void**)&KB,    g_KB);
    cudaGetSymbolAddress((void**)&P1,    g_P1);
    cudaGetSymbolAddress((void**)&P2,    g_P2);
    cudaGetSymbolAddress((void**)&Wt,    g_Wt);
    cudaGetSymbolAddress((void**)&kin,   g_kin);
    cudaGetSymbolAddress((void**)&Qg,    g_Qg);
    cudaGetSymbolAddress((void**)&Qr,    g_Qr);
    cudaGetSymbolAddress((void**)&Tg,    g_Tg);
    cudaGetSymbolAddress((void**)&Tr,    g_Tr);
    cudaGetSymbolAddress((void**)&cnt,   g_cnt);
    cudaGetSymbolAddress((void**)&psum,  g_psum);
    cudaGetSymbolAddress((void**)&psq,   g_psq);
    cudaGetSymbolAddress((void**)&psumK, g_psumK);
    cudaGetSymbolAddress((void**)&psqK,  g_psqK);
    cudaGetSymbolAddress((void**)&ss,    g_ss);

    cudaFuncSetAttribute(gemm_f16, cudaFuncAttributeMaxDynamicSharedMemorySize, GSMEM_BYTES);

    float* s_g1 = ss + 0 * EMB2_;  float* t_g1 = ss + 1 * EMB2_;
    float* s_r1 = ss + 2 * EMB2_;  float* t_r1 = ss + 3 * EMB2_;
    float* s_g2 = ss + 4 * EMB2_;  float* t_g2 = ss + 5 * EMB2_;
    float* s_r2 = ss + 6 * EMB2_;  float* t_r2 = ss + 7 * EMB2_;

    __half* Wt_g1  = Wt;
    __half* Wt_r11 = Wt_g1  + (size_t)1280 * KP1;
    __half* Wt_r12 = Wt_r11 + (size_t)1792 * KP1;
    __half* Wt_g2  = Wt_r12 + (size_t)1280 * KP1;
    __half* Wt_r21 = Wt_g2  + (size_t)1280 * KP2;
    __half* Wt_r22 = Wt_r21 + (size_t)NP_R21 * KP2;

    transpose_all<<<21392, 256>>>(g1_W, r1_W1, r1_W2, g2_W, r2_W1, r2_W2,
                                  Wt_g1, Wt_r11, Wt_r12, Wt_g2, Wt_r21, Wt_r22);
    kin_build_kernel<<<dim3(B_, K_ + 1), 256>>>(kin_in, sub, n2, phos, position,
                                                kin, X, node_feature);
    colstats_partial<<<dim3((EMB_ + 255) / 256, NCHUNK_), 256>>>(X, psum, psq, EMB_, M_ / NCHUNK_);
    finalize_stats<<<(EMB_ + 255) / 256, 256>>>(psum, psq, EMB_,
        g1_gamma, g1_beta, r1_gamma, r1_beta, s_g1, t_g1, s_r1, t_r1);
    bn_transform_kernel<<<dim3((KP1 / 2 + 255) / 256, M_), 256>>>(
        X, s_g1, t_g1, s_r1, t_r1, XA, XB, EMB_, KP1, KP1 / 2);

    // stage-1 GEMMs
    gemm_f16<<<dim3(10, 88), 256, GSMEM_BYTES>>>(XA, Wt_g1,  g1_b,  P1, nullptr, KP1, KP1, 28, 1280, 1280, 1280, nullptr, 0, nullptr, 0, nullptr);
    gemm_f16<<<dim3(14, 88), 256, GSMEM_BYTES>>>(XB, Wt_r11, r1_b1, nullptr, Y,   KP1, KP1, 28, 1792, 1792, KP1,  nullptr, 0, nullptr, 0, nullptr);
    gemm_f16<<<dim3(10, 88), 256, GSMEM_BYTES>>>(Y,  Wt_r12, r1_b2, P2, nullptr, KP1, KP1, 28, 1280, 1280, 1280, nullptr, 0, nullptr, 0, nullptr);

    combine1_kernel<<<dim3(B_, K_), 256>>>(P1, P2, node_feature, a, X);

    // stage-2 stats: X2 (gfeat), kin, props histogram
    colstats_partial<<<dim3(5, NCHUNK_), 256>>>(X, psum, psq, D_SEQ_, M_ / NCHUNK_);
    colstats_partial<<<dim3(5, 4), 256>>>(kin, psumK, psqK, D_SEQ_, B_ / 4);
    hist_kernel<<<1, 1024>>>(raw_seq, cnt);
    finalize_stats2<<<(EMB2_ + 255) / 256, 256>>>(psum, psq, psumK, psqK, cnt,
        g2_gamma, g2_beta, r2_gamma, r2_beta, s_g2, t_g2, s_r2, t_r2);

    // stage-2 transforms (gfeat part + kin part) and props tables
    bn_transform_kernel<<<dim3(3, M_), 256>>>(
        X, s_g2, t_g2, s_r2, t_r2, XA, XB, D_SEQ_, D_SEQ_, D_SEQ_ / 2);
    bn_transform_kernel<<<dim3(3, B_), 256>>>(
        kin, s_g2 + D_SEQ_, t_g2 + D_SEQ_, s_r2 + D_SEQ_, t_r2 + D_SEQ_,
        KA, KB, D_SEQ_, D_SEQ_, D_SEQ_ / 2);
    props_table<<<(21 * 1280 + 255) / 256, 256>>>(g2_W,  s_g2 + 2 * D_SEQ_, t_g2 + 2 * D_SEQ_, Tg, 1280);
    props_table<<<(21 * EMB2_ + 255) / 256, 256>>>(r2_W1, s_r2 + 2 * D_SEQ_, t_r2 + 2 * D_SEQ_, Tr, EMB2_);

    // kin GEMMs (M=1024, K=1280): Q tables
    gemm_f16<<<dim3(10, 8), 256, GSMEM_BYTES>>>(KA, Wt_g2  + 1280, nullptr, Qg, nullptr, D_SEQ_, KP2, 20, 1280, 1280, 1280, nullptr, 0, nullptr, 0, nullptr);
    gemm_f16<<<dim3(21, 8), 256, GSMEM_BYTES>>>(KB, Wt_r21 + 1280, nullptr, Qr, nullptr, D_SEQ_, KP2, 20, EMB2_, EMB2_, EMB2_, nullptr, 0, nullptr, 0, nullptr);

    // stage-2 main GEMMs (K=1280) with Q/T epilogue, then r22 (K=2624)
    gemm_f16<<<dim3(10, 88), 256, GSMEM_BYTES>>>(XA, Wt_g2,  g2_b,  P1, nullptr, D_SEQ_, KP2, 20, 1280, 1280, 1280, Qg, 1280, Tg, 1280, raw_seq);
    gemm_f16<<<dim3(21, 88), 256, GSMEM_BYTES>>>(XB, Wt_r21, r2_b1, nullptr, Y,   D_SEQ_, KP2, 20, EMB2_, KP2, KP2,  Qr, EMB2_, Tr, EMB2_, raw_seq);
    gemm_f16<<<dim3(10, 88), 256, GSMEM_BYTES>>>(Y,  Wt_r22, r2_b2, P2, nullptr, KP2, KP2, 41, 1280, 1280, 1280, nullptr, 0, nullptr, 0, nullptr);

    final_kernel<<<B_, 256>>>(P1, P2, X, a2, graph_feature);
}